// round 1
// baseline (speedup 1.0000x reference)
#include <cuda_runtime.h>
#include <math.h>

#define DIMC 768
#define NH 8
#define HD 96
#define BATCH 4
#define SEQ 2048
#define MTOT (BATCH*SEQ)

// Scratch (static device allocations; no cudaMalloc allowed)
__device__ float g_q[(size_t)BATCH*NH*SEQ*HD];
__device__ float g_k[(size_t)BATCH*NH*SEQ*HD];
__device__ float g_v[(size_t)BATCH*NH*SEQ*HD];
__device__ float g_att[(size_t)MTOT*DIMC];

// ---------------------------------------------------------------------------
// SGEMM: C[M,N] = A[M,K] @ W[N,K]^T + bias[N]
// BM=128 BN=128 BK=16, 256 threads, 8x8 per thread.
// MODE 0: A = x (param), scatter into g_q/g_k/g_v with bias (QKV)
// MODE 1: A = g_att, write C param with bias (proj)
// ---------------------------------------------------------------------------
template<int MODE>
__global__ __launch_bounds__(256)
void sgemm_kernel(const float* __restrict__ Ain, const float* __restrict__ W,
                  const float* __restrict__ bias, float* __restrict__ C)
{
    const int K = DIMC;
    __shared__ float As[16][132];
    __shared__ float Ws[16][132];

    const float* A = (MODE == 1) ? (const float*)g_att : Ain;

    int m0 = blockIdx.y * 128;
    int n0 = blockIdx.x * 128;
    int tid = threadIdx.x;
    int tx = tid & 15, ty = tid >> 4;

    float acc[8][8];
#pragma unroll
    for (int i = 0; i < 8; i++)
#pragma unroll
        for (int j = 0; j < 8; j++) acc[i][j] = 0.f;

    for (int k0 = 0; k0 < K; k0 += 16) {
#pragma unroll
        for (int p = 0; p < 2; p++) {
            int f = tid + p * 256;
            int r = f >> 2;
            int c = (f & 3) * 4;
            float4 va = *(const float4*)(A + (size_t)(m0 + r) * K + k0 + c);
            As[c+0][r] = va.x; As[c+1][r] = va.y; As[c+2][r] = va.z; As[c+3][r] = va.w;
            float4 vb = *(const float4*)(W + (size_t)(n0 + r) * K + k0 + c);
            Ws[c+0][r] = vb.x; Ws[c+1][r] = vb.y; Ws[c+2][r] = vb.z; Ws[c+3][r] = vb.w;
        }
        __syncthreads();
#pragma unroll
        for (int kk = 0; kk < 16; kk++) {
            float a[8], b[8];
            *(float4*)&a[0] = *(const float4*)&As[kk][ty*8];
            *(float4*)&a[4] = *(const float4*)&As[kk][ty*8+4];
            *(float4*)&b[0] = *(const float4*)&Ws[kk][tx*8];
            *(float4*)&b[4] = *(const float4*)&Ws[kk][tx*8+4];
#pragma unroll
            for (int i = 0; i < 8; i++)
#pragma unroll
                for (int j = 0; j < 8; j++)
                    acc[i][j] += a[i] * b[j];
        }
        __syncthreads();
    }

    if (MODE == 0) {
#pragma unroll
        for (int i = 0; i < 8; i++) {
            int m = m0 + ty*8 + i;
            int bb = m >> 11;         // m / SEQ
            int t  = m & (SEQ - 1);
#pragma unroll
            for (int j = 0; j < 8; j++) {
                int n = n0 + tx*8 + j;
                float val = acc[i][j] + bias[n];
                int s  = n / DIMC;
                int rr = n - s * DIMC;
                int h  = rr / HD;
                int d  = rr - h * HD;
                float* dst = (s == 0) ? g_q : (s == 1) ? g_k : g_v;
                dst[((size_t)(bb*NH + h)*SEQ + t)*HD + d] = val;
            }
        }
    } else {
#pragma unroll
        for (int i = 0; i < 8; i++) {
            int m = m0 + ty*8 + i;
#pragma unroll
            for (int j = 0; j < 8; j++) {
                int n = n0 + tx*8 + j;
                C[(size_t)m * DIMC + n] = acc[i][j] + bias[n];
            }
        }
    }
}

// ---------------------------------------------------------------------------
// RoPE in place on g_q, g_k. One thread per (bh, t, j<48) pair.
// ---------------------------------------------------------------------------
__global__ __launch_bounds__(256)
void rope_kernel()
{
    int idx = blockIdx.x * blockDim.x + threadIdx.x;   // [0, B*NH*SEQ*48)
    int j    = idx % 48;
    int rest = idx / 48;
    int t    = rest & (SEQ - 1);
    int bh   = rest >> 11;

    // freq = 10000^(-2j/96) = 2^(-(2j/96)*log2(10000))
    float freq = exp2f(-(2.f * j / 96.f) * 13.287712379549449f);
    float ang = (float)t * freq;
    float sn, cs;
    sincosf(ang, &sn, &cs);

    size_t base = ((size_t)bh * SEQ + t) * HD;
    float q1 = g_q[base + j], q2 = g_q[base + j + 48];
    g_q[base + j]      = q1 * cs - q2 * sn;
    g_q[base + j + 48] = q2 * cs + q1 * sn;
    float k1 = g_k[base + j], k2 = g_k[base + j + 48];
    g_k[base + j]      = k1 * cs - k2 * sn;
    g_k[base + j + 48] = k2 * cs + k1 * sn;
}

// ---------------------------------------------------------------------------
// Flash-style causal attention. Block = (b, h, qtile of 64). 256 threads.
// Thread (ty,tx) in 16x16 grid: owns S rows 4ty..4ty+3, S cols 4tx..4tx+3,
// O cols 6tx..6tx+5. Rows reduced across 16 lanes (half-warp shuffles).
// ---------------------------------------------------------------------------
#define QT 64
#define KT 64
#define ATTN_SMEM_BYTES ((2*96*68 + 64*96 + 64*65) * 4)

__global__ __launch_bounds__(256)
void attn_kernel()
{
    extern __shared__ float sm[];
    float (*Qst)[68] = (float(*)[68])sm;                         // [96][68] d-major
    float (*Kst)[68] = (float(*)[68])(sm + 96*68);               // [96][68]
    float (*Vs)[96]  = (float(*)[96])(sm + 2*96*68);             // [64][96] k-major
    float (*Ps)[65]  = (float(*)[65])(sm + 2*96*68 + 64*96);     // [64][65]

    int qt = blockIdx.x, h = blockIdx.y, b = blockIdx.z;
    int tid = threadIdx.x;
    int tx = tid & 15, ty = tid >> 4;
    const float scale = rsqrtf((float)HD);

    const float* Qg = g_q + ((size_t)(b*NH + h)*SEQ + (size_t)qt*QT) * HD;
    const float* Kg = g_k + ((size_t)(b*NH + h)*SEQ) * HD;
    const float* Vg = g_v + ((size_t)(b*NH + h)*SEQ) * HD;

    // Load + transpose + prescale Q tile
    for (int f = tid; f < 64*24; f += 256) {
        int r = f / 24, c = (f % 24) * 4;
        float4 v = *(const float4*)(Qg + r*96 + c);
        Qst[c+0][r] = v.x * scale;
        Qst[c+1][r] = v.y * scale;
        Qst[c+2][r] = v.z * scale;
        Qst[c+3][r] = v.w * scale;
    }

    float o[4][6];
    float mrow[4], lrow[4];
#pragma unroll
    for (int i = 0; i < 4; i++) {
        mrow[i] = -1e30f; lrow[i] = 0.f;
#pragma unroll
        for (int j = 0; j < 6; j++) o[i][j] = 0.f;
    }
    __syncthreads();

    for (int kt = 0; kt <= qt; kt++) {
        const float* Kt = Kg + (size_t)kt * KT * HD;
        const float* Vt = Vg + (size_t)kt * KT * HD;
        for (int f = tid; f < 64*24; f += 256) {
            int r = f / 24, c = (f % 24) * 4;
            float4 v = *(const float4*)(Kt + r*96 + c);
            Kst[c+0][r] = v.x; Kst[c+1][r] = v.y; Kst[c+2][r] = v.z; Kst[c+3][r] = v.w;
            float4 w = *(const float4*)(Vt + r*96 + c);
            *(float4*)&Vs[r][c] = w;
        }
        __syncthreads();

        // S = (Q*scale) @ K^T  (4x4 per thread)
        float s[4][4];
#pragma unroll
        for (int i = 0; i < 4; i++)
#pragma unroll
            for (int j = 0; j < 4; j++) s[i][j] = 0.f;

#pragma unroll 8
        for (int d = 0; d < 96; d++) {
            float4 qf = *(const float4*)&Qst[d][ty*4];
            float4 kf = *(const float4*)&Kst[d][tx*4];
            float qa[4] = {qf.x, qf.y, qf.z, qf.w};
            float ka[4] = {kf.x, kf.y, kf.z, kf.w};
#pragma unroll
            for (int i = 0; i < 4; i++)
#pragma unroll
                for (int j = 0; j < 4; j++)
                    s[i][j] += qa[i] * ka[j];
        }

        if (kt == qt) {
#pragma unroll
            for (int i = 0; i < 4; i++)
#pragma unroll
                for (int j = 0; j < 4; j++)
                    if (tx*4 + j > ty*4 + i) s[i][j] = -1e30f;
        }

        // Online softmax (row stats shared across the 16 lanes of a half-warp)
#pragma unroll
        for (int i = 0; i < 4; i++) {
            float mx = fmaxf(fmaxf(s[i][0], s[i][1]), fmaxf(s[i][2], s[i][3]));
#pragma unroll
            for (int off = 8; off >= 1; off >>= 1)
                mx = fmaxf(mx, __shfl_xor_sync(0xffffffffu, mx, off));
            float mnew  = fmaxf(mrow[i], mx);
            float alpha = expf(mrow[i] - mnew);
            float ps = 0.f;
#pragma unroll
            for (int j = 0; j < 4; j++) {
                float p = expf(s[i][j] - mnew);
                Ps[ty*4 + i][tx*4 + j] = p;
                ps += p;
            }
#pragma unroll
            for (int off = 8; off >= 1; off >>= 1)
                ps += __shfl_xor_sync(0xffffffffu, ps, off);
            lrow[i] = lrow[i] * alpha + ps;
            mrow[i] = mnew;
#pragma unroll
            for (int j = 0; j < 6; j++) o[i][j] *= alpha;
        }
        __syncthreads();

        // O += P @ V   (4 rows x 6 cols per thread)
#pragma unroll 4
        for (int k = 0; k < 64; k++) {
            float p0 = Ps[ty*4+0][k];
            float p1 = Ps[ty*4+1][k];
            float p2 = Ps[ty*4+2][k];
            float p3 = Ps[ty*4+3][k];
            float vv[6];
#pragma unroll
            for (int j = 0; j < 6; j++) vv[j] = Vs[k][tx*6 + j];
#pragma unroll
            for (int j = 0; j < 6; j++) {
                o[0][j] += p0 * vv[j];
                o[1][j] += p1 * vv[j];
                o[2][j] += p2 * vv[j];
                o[3][j] += p3 * vv[j];
            }
        }
        __syncthreads();
    }

    // Write O / l into g_att [B, T, DIM] layout (col = h*96 + d)
#pragma unroll
    for (int i = 0; i < 4; i++) {
        float inv = 1.f / lrow[i];
        int t = qt*QT + ty*4 + i;
        float* dst = g_att + ((size_t)b*SEQ + t)*DIMC + h*HD + tx*6;
#pragma unroll
        for (int j = 0; j < 6; j++) dst[j] = o[i][j] * inv;
    }
}

// ---------------------------------------------------------------------------
// Launch
// Inputs: 0=x [4,2048,768], 1=mask (ignored, known causal), 2=w_qkv [2304,768],
//         3=b_qkv [2304], 4=w_proj [768,768], 5=b_proj [768]
// ---------------------------------------------------------------------------
extern "C" void kernel_launch(void* const* d_in, const int* in_sizes, int n_in,
                              void* d_out, int out_size)
{
    const float* x      = (const float*)d_in[0];
    const float* w_qkv  = (const float*)d_in[2];
    const float* b_qkv  = (const float*)d_in[3];
    const float* w_proj = (const float*)d_in[4];
    const float* b_proj = (const float*)d_in[5];
    float* out = (float*)d_out;

    cudaFuncSetAttribute(attn_kernel,
                         cudaFuncAttributeMaxDynamicSharedMemorySize,
                         ATTN_SMEM_BYTES);

    // QKV: M=8192, N=2304
    sgemm_kernel<0><<<dim3(2304/128, MTOT/128), 256>>>(x, w_qkv, b_qkv, nullptr);

    // RoPE: B*NH*SEQ*48 threads
    rope_kernel<<<(BATCH*NH*SEQ*48)/256, 256>>>();

    // Attention: (qtile, head, batch)
    attn_kernel<<<dim3(SEQ/QT, NH, BATCH), 256, ATTN_SMEM_BYTES>>>();

    // Projection: M=8192, N=768
    sgemm_kernel<1><<<dim3(DIMC/128, MTOT/128), 256>>>(nullptr, w_proj, b_proj, out);
}

// round 3
// speedup vs baseline: 1.8419x; 1.8419x over previous
#include <cuda_runtime.h>
#include <math.h>
#include <stdint.h>

#define DIMC 768
#define NH 8
#define HD 96
#define BATCH 4
#define SEQ 2048
#define MTOT (BATCH*SEQ)

// Scratch (static device arrays; no cudaMalloc allowed)
__device__ float g_q[(size_t)BATCH*NH*SEQ*HD];
__device__ float g_k[(size_t)BATCH*NH*SEQ*HD];
__device__ float g_v[(size_t)BATCH*NH*SEQ*HD];
__device__ float g_att[(size_t)MTOT*DIMC];

// ---------------------------------------------------------------------------
// helpers
// ---------------------------------------------------------------------------
__device__ __forceinline__ uint32_t smem_u32(const void* p) {
    uint32_t a;
    asm("{ .reg .u64 t; cvta.to.shared.u64 t, %1; cvt.u32.u64 %0, t; }" : "=r"(a) : "l"(p));
    return a;
}
__device__ __forceinline__ void cp16(uint32_t s, const float* g) {
    asm volatile("cp.async.ca.shared.global [%0], [%1], 16;" :: "r"(s), "l"(g) : "memory");
}
__device__ __forceinline__ void cp_commit() {
    asm volatile("cp.async.commit_group;" ::: "memory");
}
__device__ __forceinline__ void cp_wait0() {
    asm volatile("cp.async.wait_group 0;" ::: "memory");
}
__device__ __forceinline__ uint32_t f2tf(float x) {
    uint32_t r;
    asm("cvt.rna.tf32.f32 %0, %1;" : "=r"(r) : "f"(x));
    return r;
}
// D += A(16x8) * B(8x8), tf32 inputs, f32 accum
__device__ __forceinline__ void mma8(float d[4], uint32_t a0, uint32_t a1,
                                     uint32_t a2, uint32_t a3,
                                     uint32_t b0, uint32_t b1) {
    asm volatile(
        "mma.sync.aligned.m16n8k8.row.col.f32.tf32.tf32.f32 "
        "{%0,%1,%2,%3},{%4,%5,%6,%7},{%8,%9},{%0,%1,%2,%3};"
        : "+f"(d[0]), "+f"(d[1]), "+f"(d[2]), "+f"(d[3])
        : "r"(a0), "r"(a1), "r"(a2), "r"(a3), "r"(b0), "r"(b1));
}

// ---------------------------------------------------------------------------
// GEMM via mma.sync tf32 with hi/lo split (fp32-accurate):
// C[M,N] = A[M,768] @ W[N,768]^T + bias
// CTA tile 128x128, 8 warps in 2(m) x 4(n), warp tile 64x32.
// MODE 0: A = x, scatter epilogue into g_q/g_k/g_v. MODE 1: A = g_att -> C.
// ---------------------------------------------------------------------------
#define SLD 20   // smem row stride (floats): 16 + 4 pad -> conflict-free frags

template<int MODE>
__global__ __launch_bounds__(256, 1)
void gemm_mma(const float* __restrict__ Ain, const float* __restrict__ W,
              const float* __restrict__ bias, float* __restrict__ Cout)
{
    __shared__ float As[2][128][SLD];
    __shared__ float Ws[2][128][SLD];

    const float* A = (MODE == 1) ? (const float*)g_att : Ain;

    int tid = threadIdx.x;
    int lane = tid & 31;
    int wid = tid >> 5;
    int g = lane >> 2, j = lane & 3;
    int wm = wid & 1, wn = wid >> 1;      // 2 x 4 warp grid
    int m0 = blockIdx.y * 128;
    int n0 = blockIdx.x * 128;

    uint32_t asb = smem_u32(&As[0][0][0]);
    uint32_t wsb = smem_u32(&Ws[0][0][0]);

    float Cf[4][4][4];
#pragma unroll
    for (int mt = 0; mt < 4; mt++)
#pragma unroll
        for (int nt = 0; nt < 4; nt++)
#pragma unroll
            for (int r = 0; r < 4; r++) Cf[mt][nt][r] = 0.f;

    auto load_chunk = [&](int c, int buf) {
#pragma unroll
        for (int p = 0; p < 2; p++) {
            int f = tid + p * 256;
            int row = f >> 2;
            int col = (f & 3) * 4;
            uint32_t so = (uint32_t)(((buf * 128 + row) * SLD + col) * 4);
            cp16(asb + so, A + (size_t)(m0 + row) * DIMC + c * 16 + col);
            cp16(wsb + so, W + (size_t)(n0 + row) * DIMC + c * 16 + col);
        }
        cp_commit();
    };

    load_chunk(0, 0);
    cp_wait0();
    __syncthreads();

    for (int c = 0; c < DIMC / 16; c++) {
        int buf = c & 1;
        if (c + 1 < DIMC / 16) load_chunk(c + 1, buf ^ 1);

#pragma unroll
        for (int ks = 0; ks < 2; ks++) {
            int k0 = ks * 8;
            uint32_t ah[4][4], al[4][4];
#pragma unroll
            for (int mt = 0; mt < 4; mt++) {
                int r0 = wm * 64 + mt * 16 + g;
                float x0 = As[buf][r0][k0 + j];
                float x1 = As[buf][r0 + 8][k0 + j];
                float x2 = As[buf][r0][k0 + j + 4];
                float x3 = As[buf][r0 + 8][k0 + j + 4];
                ah[mt][0] = f2tf(x0); al[mt][0] = __float_as_uint(x0 - __uint_as_float(ah[mt][0]));
                ah[mt][1] = f2tf(x1); al[mt][1] = __float_as_uint(x1 - __uint_as_float(ah[mt][1]));
                ah[mt][2] = f2tf(x2); al[mt][2] = __float_as_uint(x2 - __uint_as_float(ah[mt][2]));
                ah[mt][3] = f2tf(x3); al[mt][3] = __float_as_uint(x3 - __uint_as_float(ah[mt][3]));
            }
            uint32_t bh[4][2], bl[4][2];
#pragma unroll
            for (int nt = 0; nt < 4; nt++) {
                int rn = wn * 32 + nt * 8 + g;
                float y0 = Ws[buf][rn][k0 + j];
                float y1 = Ws[buf][rn][k0 + j + 4];
                bh[nt][0] = f2tf(y0); bl[nt][0] = __float_as_uint(y0 - __uint_as_float(bh[nt][0]));
                bh[nt][1] = f2tf(y1); bl[nt][1] = __float_as_uint(y1 - __uint_as_float(bh[nt][1]));
            }
#pragma unroll
            for (int mt = 0; mt < 4; mt++)
#pragma unroll
                for (int nt = 0; nt < 4; nt++) {
                    mma8(Cf[mt][nt], ah[mt][0], ah[mt][1], ah[mt][2], ah[mt][3], bh[nt][0], bh[nt][1]);
                    mma8(Cf[mt][nt], ah[mt][0], ah[mt][1], ah[mt][2], ah[mt][3], bl[nt][0], bl[nt][1]);
                    mma8(Cf[mt][nt], al[mt][0], al[mt][1], al[mt][2], al[mt][3], bh[nt][0], bh[nt][1]);
                }
        }
        cp_wait0();
        __syncthreads();
    }

    // epilogue
#pragma unroll
    for (int mt = 0; mt < 4; mt++) {
        int row0 = m0 + wm * 64 + mt * 16 + g;
#pragma unroll
        for (int nt = 0; nt < 4; nt++) {
            int col = n0 + wn * 32 + nt * 8 + 2 * j;
            float b0 = bias[col], b1 = bias[col + 1];
            float2 v0 = make_float2(Cf[mt][nt][0] + b0, Cf[mt][nt][1] + b1);
            float2 v1 = make_float2(Cf[mt][nt][2] + b0, Cf[mt][nt][3] + b1);
            if (MODE == 1) {
                *(float2*)(Cout + (size_t)row0 * DIMC + col) = v0;
                *(float2*)(Cout + (size_t)(row0 + 8) * DIMC + col) = v1;
            } else {
                int s = (col >= 2 * DIMC) ? 2 : (col >= DIMC ? 1 : 0);
                int rr = col - s * DIMC;
                int h = rr / HD;
                int d = rr - h * HD;
                float* base = (s == 0) ? g_q : (s == 1) ? g_k : g_v;
                int bb0 = row0 >> 11, t0 = row0 & (SEQ - 1);
                int r1 = row0 + 8;
                int bb1 = r1 >> 11, t1 = r1 & (SEQ - 1);
                *(float2*)(base + ((size_t)(bb0 * NH + h) * SEQ + t0) * HD + d) = v0;
                *(float2*)(base + ((size_t)(bb1 * NH + h) * SEQ + t1) * HD + d) = v1;
            }
        }
    }
}

// ---------------------------------------------------------------------------
// RoPE in place on g_q, g_k.
// ---------------------------------------------------------------------------
__global__ __launch_bounds__(256)
void rope_kernel()
{
    int idx = blockIdx.x * blockDim.x + threadIdx.x;
    int j = idx % 48;
    int rest = idx / 48;
    int t = rest & (SEQ - 1);
    int bh = rest >> 11;

    float freq = exp2f(-(2.f * j / 96.f) * 13.287712379549449f);
    float ang = (float)t * freq;
    float sn, cs;
    sincosf(ang, &sn, &cs);

    size_t base = ((size_t)bh * SEQ + t) * HD;
    float q1 = g_q[base + j], q2 = g_q[base + j + 48];
    g_q[base + j]      = q1 * cs - q2 * sn;
    g_q[base + j + 48] = q2 * cs + q1 * sn;
    float k1 = g_k[base + j], k2 = g_k[base + j + 48];
    g_k[base + j]      = k1 * cs - k2 * sn;
    g_k[base + j + 48] = k2 * cs + k1 * sn;
}

// ---------------------------------------------------------------------------
// Flash attention via mma.sync tf32.
// Block = (qtile 128, h, b), 256 threads = 8 warps; warp w owns Q rows w*16..+16.
// Per 64-key tile: S = Q@K^T (m16,n64,k96), online softmax on C-frags,
// P relayout via shuffles, O += P@V (m16,n96,k64).
// ---------------------------------------------------------------------------
#define QLD 100
#define KLD 100
#define VLD 104
#define ATTN_SMEM ((128*QLD + 64*KLD + 64*VLD) * 4)   // 103424

__global__ __launch_bounds__(256, 1)
void attn_mma()
{
    extern __shared__ float smf[];
    float* Qs = smf;                       // [128][QLD]
    float* Ks = smf + 128 * QLD;           // [64][KLD]
    float* Vs = smf + 128 * QLD + 64 * KLD; // [64][VLD]

    int qt = blockIdx.x, h = blockIdx.y, b = blockIdx.z;
    int tid = threadIdx.x;
    int lane = tid & 31;
    int wid = tid >> 5;
    int g = lane >> 2, j = lane & 3;
    const float scale = rsqrtf((float)HD);

    const float* Qg = g_q + ((size_t)(b * NH + h) * SEQ + (size_t)qt * 128) * HD;
    const float* Kg = g_k + ((size_t)(b * NH + h) * SEQ) * HD;
    const float* Vg = g_v + ((size_t)(b * NH + h) * SEQ) * HD;

    // Load + prescale Q tile: 128 rows x 96 cols
    for (int f = tid; f < 128 * 24; f += 256) {
        int r = f / 24, c4 = (f % 24) * 4;
        float4 v = *(const float4*)(Qg + (size_t)r * HD + c4);
        v.x *= scale; v.y *= scale; v.z *= scale; v.w *= scale;
        *(float4*)(Qs + r * QLD + c4) = v;
    }

    float m0r = -1e30f, m1r = -1e30f, l0r = 0.f, l1r = 0.f;
    float O[12][4];
#pragma unroll
    for (int nt = 0; nt < 12; nt++)
#pragma unroll
        for (int r = 0; r < 4; r++) O[nt][r] = 0.f;

    int row0 = qt * 128 + wid * 16 + g;   // global query row of c0/c1
    int nkt = 2 * qt + 2;

    __syncthreads();

    for (int kt = 0; kt < nkt; kt++) {
        __syncthreads();   // previous iteration done reading Ks/Vs
        for (int f = tid; f < 64 * 24; f += 256) {
            int r = f / 24, c4 = (f % 24) * 4;
            const float* kp = Kg + ((size_t)kt * 64 + r) * HD + c4;
            const float* vp = Vg + ((size_t)kt * 64 + r) * HD + c4;
            *(float4*)(Ks + r * KLD + c4) = *(const float4*)kp;
            *(float4*)(Vs + r * VLD + c4) = *(const float4*)vp;
        }
        __syncthreads();

        // ---- S = Q @ K^T ----
        float S[8][4];
#pragma unroll
        for (int nt = 0; nt < 8; nt++)
#pragma unroll
            for (int r = 0; r < 4; r++) S[nt][r] = 0.f;

#pragma unroll
        for (int ks = 0; ks < 12; ks++) {
            int k0 = ks * 8;
            int qr = wid * 16 + g;
            uint32_t a0 = f2tf(Qs[qr * QLD + k0 + j]);
            uint32_t a1 = f2tf(Qs[(qr + 8) * QLD + k0 + j]);
            uint32_t a2 = f2tf(Qs[qr * QLD + k0 + j + 4]);
            uint32_t a3 = f2tf(Qs[(qr + 8) * QLD + k0 + j + 4]);
#pragma unroll
            for (int nt = 0; nt < 8; nt++) {
                uint32_t b0 = f2tf(Ks[(nt * 8 + g) * KLD + k0 + j]);
                uint32_t b1 = f2tf(Ks[(nt * 8 + g) * KLD + k0 + j + 4]);
                mma8(S[nt], a0, a1, a2, a3, b0, b1);
            }
        }

        // ---- causal mask (only possibly-clipped tiles) ----
        if (kt >= nkt - 2) {
            int colb = kt * 64;
#pragma unroll
            for (int nt = 0; nt < 8; nt++) {
                int c0 = colb + nt * 8 + 2 * j;
                if (c0 > row0)     S[nt][0] = -1e30f;
                if (c0 + 1 > row0) S[nt][1] = -1e30f;
                if (c0 > row0 + 8)     S[nt][2] = -1e30f;
                if (c0 + 1 > row0 + 8) S[nt][3] = -1e30f;
            }
        }

        // ---- online softmax ----
        float mx0 = -1e30f, mx1 = -1e30f;
#pragma unroll
        for (int nt = 0; nt < 8; nt++) {
            mx0 = fmaxf(mx0, fmaxf(S[nt][0], S[nt][1]));
            mx1 = fmaxf(mx1, fmaxf(S[nt][2], S[nt][3]));
        }
        mx0 = fmaxf(mx0, __shfl_xor_sync(0xffffffffu, mx0, 1));
        mx0 = fmaxf(mx0, __shfl_xor_sync(0xffffffffu, mx0, 2));
        mx1 = fmaxf(mx1, __shfl_xor_sync(0xffffffffu, mx1, 1));
        mx1 = fmaxf(mx1, __shfl_xor_sync(0xffffffffu, mx1, 2));

        float mn0 = fmaxf(m0r, mx0), mn1 = fmaxf(m1r, mx1);
        float al0 = __expf(m0r - mn0), al1 = __expf(m1r - mn1);
        float s0 = 0.f, s1 = 0.f;
#pragma unroll
        for (int nt = 0; nt < 8; nt++) {
            S[nt][0] = __expf(S[nt][0] - mn0);
            S[nt][1] = __expf(S[nt][1] - mn0);
            S[nt][2] = __expf(S[nt][2] - mn1);
            S[nt][3] = __expf(S[nt][3] - mn1);
            s0 += S[nt][0] + S[nt][1];
            s1 += S[nt][2] + S[nt][3];
        }
        s0 += __shfl_xor_sync(0xffffffffu, s0, 1);
        s0 += __shfl_xor_sync(0xffffffffu, s0, 2);
        s1 += __shfl_xor_sync(0xffffffffu, s1, 1);
        s1 += __shfl_xor_sync(0xffffffffu, s1, 2);
        l0r = l0r * al0 + s0;
        l1r = l1r * al1 + s1;
        m0r = mn0; m1r = mn1;
#pragma unroll
        for (int nt = 0; nt < 12; nt++) {
            O[nt][0] *= al0; O[nt][1] *= al0;
            O[nt][2] *= al1; O[nt][3] *= al1;
        }

        // ---- O += P @ V ----
        int src_lo = (lane & ~3) | (j >> 1);
        int par = j & 1;
#pragma unroll
        for (int ks = 0; ks < 8; ks++) {
            // relayout P (C-frag of tile ks) -> A-frag via shuffles
            float p00 = __shfl_sync(0xffffffffu, S[ks][0], src_lo);
            float p01 = __shfl_sync(0xffffffffu, S[ks][1], src_lo);
            float p10 = __shfl_sync(0xffffffffu, S[ks][0], src_lo + 2);
            float p11 = __shfl_sync(0xffffffffu, S[ks][1], src_lo + 2);
            float p20 = __shfl_sync(0xffffffffu, S[ks][2], src_lo);
            float p21 = __shfl_sync(0xffffffffu, S[ks][3], src_lo);
            float p30 = __shfl_sync(0xffffffffu, S[ks][2], src_lo + 2);
            float p31 = __shfl_sync(0xffffffffu, S[ks][3], src_lo + 2);
            uint32_t a0 = f2tf(par ? p01 : p00);   // (row g,   col j)
            uint32_t a1 = f2tf(par ? p21 : p20);   // (row g+8, col j)
            uint32_t a2 = f2tf(par ? p11 : p10);   // (row g,   col j+4)
            uint32_t a3 = f2tf(par ? p31 : p30);   // (row g+8, col j+4)
#pragma unroll
            for (int nt = 0; nt < 12; nt++) {
                uint32_t b0 = f2tf(Vs[(ks * 8 + j) * VLD + nt * 8 + g]);
                uint32_t b1 = f2tf(Vs[(ks * 8 + j + 4) * VLD + nt * 8 + g]);
                mma8(O[nt], a0, a1, a2, a3, b0, b1);
            }
        }
    }

    // ---- writeback O / l -> g_att [B,T,768] ----
    float inv0 = 1.f / l0r, inv1 = 1.f / l1r;
    float* outb = g_att + ((size_t)b * SEQ + row0) * DIMC + h * HD;
#pragma unroll
    for (int nt = 0; nt < 12; nt++) {
        int d = nt * 8 + 2 * j;
        *(float2*)(outb + d) = make_float2(O[nt][0] * inv0, O[nt][1] * inv0);
        *(float2*)(outb + (size_t)8 * DIMC + d) = make_float2(O[nt][2] * inv1, O[nt][3] * inv1);
    }
}

// ---------------------------------------------------------------------------
// Launch
// Inputs: 0=x, 1=mask (ignored, causal), 2=w_qkv, 3=b_qkv, 4=w_proj, 5=b_proj
// ---------------------------------------------------------------------------
extern "C" void kernel_launch(void* const* d_in, const int* in_sizes, int n_in,
                              void* d_out, int out_size)
{
    const float* x      = (const float*)d_in[0];
    const float* w_qkv  = (const float*)d_in[2];
    const float* b_qkv  = (const float*)d_in[3];
    const float* w_proj = (const float*)d_in[4];
    const float* b_proj = (const float*)d_in[5];
    float* out = (float*)d_out;

    cudaFuncSetAttribute(attn_mma, cudaFuncAttributeMaxDynamicSharedMemorySize,
                         ATTN_SMEM);

    // QKV: M=8192, N=2304
    gemm_mma<0><<<dim3(2304 / 128, MTOT / 128), 256>>>(x, w_qkv, b_qkv, nullptr);

    // RoPE
    rope_kernel<<<(BATCH * NH * SEQ * 48) / 256, 256>>>();

    // Attention
    attn_mma<<<dim3(SEQ / 128, NH, BATCH), 256, ATTN_SMEM>>>();

    // Projection: M=8192, N=768
    gemm_mma<1><<<dim3(DIMC / 128, MTOT / 128), 256>>>(nullptr, w_proj, b_proj, out);
}

// round 4
// speedup vs baseline: 1.9421x; 1.0544x over previous
#include <cuda_runtime.h>
#include <math.h>
#include <stdint.h>

#define DIMC 768
#define NH 8
#define HD 96
#define BATCH 4
#define SEQ 2048
#define MTOT (BATCH*SEQ)

// Scratch (static device arrays; no cudaMalloc allowed)
__device__ float g_q[(size_t)BATCH*NH*SEQ*HD];
__device__ float g_k[(size_t)BATCH*NH*SEQ*HD];
__device__ float g_v[(size_t)BATCH*NH*SEQ*HD];
__device__ float g_att[(size_t)MTOT*DIMC];

// ---------------------------------------------------------------------------
// helpers
// ---------------------------------------------------------------------------
__device__ __forceinline__ uint32_t smem_u32(const void* p) {
    uint32_t a;
    asm("{ .reg .u64 t; cvta.to.shared.u64 t, %1; cvt.u32.u64 %0, t; }" : "=r"(a) : "l"(p));
    return a;
}
__device__ __forceinline__ void cp16(uint32_t s, const float* g) {
    asm volatile("cp.async.ca.shared.global [%0], [%1], 16;" :: "r"(s), "l"(g) : "memory");
}
__device__ __forceinline__ void cp_commit() {
    asm volatile("cp.async.commit_group;" ::: "memory");
}
__device__ __forceinline__ void cp_wait0() {
    asm volatile("cp.async.wait_group 0;" ::: "memory");
}
__device__ __forceinline__ uint32_t f2tf(float x) {
    uint32_t r;
    asm("cvt.rna.tf32.f32 %0, %1;" : "=r"(r) : "f"(x));
    return r;
}
// pack two f32 -> bf16x2 (x0 -> low half, x1 -> high half)
__device__ __forceinline__ uint32_t pack_bf2(float x0, float x1) {
    uint32_t r;
    asm("cvt.rn.bf16x2.f32 %0, %1, %2;" : "=r"(r) : "f"(x1), "f"(x0));
    return r;
}
// split pair into (hi bf16x2, lo bf16x2)
__device__ __forceinline__ void split_bf2(float x0, float x1, uint32_t& hi, uint32_t& lo) {
    hi = pack_bf2(x0, x1);
    float h0 = __uint_as_float(hi << 16);
    float h1 = __uint_as_float(hi & 0xffff0000u);
    lo = pack_bf2(x0 - h0, x1 - h1);
}
// D += A(16x8) * B(8x8), tf32 inputs, f32 accum
__device__ __forceinline__ void mma_tf(float d[4], uint32_t a0, uint32_t a1,
                                       uint32_t a2, uint32_t a3,
                                       uint32_t b0, uint32_t b1) {
    asm volatile(
        "mma.sync.aligned.m16n8k8.row.col.f32.tf32.tf32.f32 "
        "{%0,%1,%2,%3},{%4,%5,%6,%7},{%8,%9},{%0,%1,%2,%3};"
        : "+f"(d[0]), "+f"(d[1]), "+f"(d[2]), "+f"(d[3])
        : "r"(a0), "r"(a1), "r"(a2), "r"(a3), "r"(b0), "r"(b1));
}
// D += A(16x16) * B(16x8), bf16 inputs, f32 accum
__device__ __forceinline__ void mma_bf(float d[4], uint32_t a0, uint32_t a1,
                                       uint32_t a2, uint32_t a3,
                                       uint32_t b0, uint32_t b1) {
    asm volatile(
        "mma.sync.aligned.m16n8k16.row.col.f32.bf16.bf16.f32 "
        "{%0,%1,%2,%3},{%4,%5,%6,%7},{%8,%9},{%0,%1,%2,%3};"
        : "+f"(d[0]), "+f"(d[1]), "+f"(d[2]), "+f"(d[3])
        : "r"(a0), "r"(a1), "r"(a2), "r"(a3), "r"(b0), "r"(b1));
}

// ---------------------------------------------------------------------------
// GEMM via mma.sync bf16 with hi/lo split (near-fp32 accuracy):
// C[M,N] = A[M,768] @ W[N,768]^T + bias
// CTA tile 128x128, 8 warps in 2(m) x 4(n), warp tile 64x32, BK=16 (one k16).
// MODE 0: A = x, scatter epilogue into g_q/g_k/g_v. MODE 1: A = g_att -> C.
// ---------------------------------------------------------------------------
#define SLD 20   // smem row stride (floats): 16 + 4 pad -> conflict-free frags

template<int MODE>
__global__ __launch_bounds__(256, 1)
void gemm_mma(const float* __restrict__ Ain, const float* __restrict__ W,
              const float* __restrict__ bias, float* __restrict__ Cout)
{
    __shared__ float As[2][128][SLD];
    __shared__ float Ws[2][128][SLD];

    const float* A = (MODE == 1) ? (const float*)g_att : Ain;

    int tid = threadIdx.x;
    int lane = tid & 31;
    int wid = tid >> 5;
    int g = lane >> 2, j = lane & 3;
    int wm = wid & 1, wn = wid >> 1;      // 2 x 4 warp grid
    int m0 = blockIdx.y * 128;
    int n0 = blockIdx.x * 128;

    uint32_t asb = smem_u32(&As[0][0][0]);
    uint32_t wsb = smem_u32(&Ws[0][0][0]);

    float Cf[4][4][4];
#pragma unroll
    for (int mt = 0; mt < 4; mt++)
#pragma unroll
        for (int nt = 0; nt < 4; nt++)
#pragma unroll
            for (int r = 0; r < 4; r++) Cf[mt][nt][r] = 0.f;

    auto load_chunk = [&](int c, int buf) {
#pragma unroll
        for (int p = 0; p < 2; p++) {
            int f = tid + p * 256;
            int row = f >> 2;
            int col = (f & 3) * 4;
            uint32_t so = (uint32_t)(((buf * 128 + row) * SLD + col) * 4);
            cp16(asb + so, A + (size_t)(m0 + row) * DIMC + c * 16 + col);
            cp16(wsb + so, W + (size_t)(n0 + row) * DIMC + c * 16 + col);
        }
        cp_commit();
    };

    load_chunk(0, 0);
    cp_wait0();
    __syncthreads();

    for (int c = 0; c < DIMC / 16; c++) {
        int buf = c & 1;
        if (c + 1 < DIMC / 16) load_chunk(c + 1, buf ^ 1);

        // A fragments (bf16 hi/lo), one k16 slice
        uint32_t ah[4][4], al[4][4];
#pragma unroll
        for (int mt = 0; mt < 4; mt++) {
            int r0 = wm * 64 + mt * 16 + g;
            float x00 = As[buf][r0][2*j],     x01 = As[buf][r0][2*j+1];
            float x10 = As[buf][r0+8][2*j],   x11 = As[buf][r0+8][2*j+1];
            float x20 = As[buf][r0][2*j+8],   x21 = As[buf][r0][2*j+9];
            float x30 = As[buf][r0+8][2*j+8], x31 = As[buf][r0+8][2*j+9];
            split_bf2(x00, x01, ah[mt][0], al[mt][0]);
            split_bf2(x10, x11, ah[mt][1], al[mt][1]);
            split_bf2(x20, x21, ah[mt][2], al[mt][2]);
            split_bf2(x30, x31, ah[mt][3], al[mt][3]);
        }
        uint32_t bh[4][2], bl[4][2];
#pragma unroll
        for (int nt = 0; nt < 4; nt++) {
            int rn = wn * 32 + nt * 8 + g;
            float y00 = Ws[buf][rn][2*j],   y01 = Ws[buf][rn][2*j+1];
            float y10 = Ws[buf][rn][2*j+8], y11 = Ws[buf][rn][2*j+9];
            split_bf2(y00, y01, bh[nt][0], bl[nt][0]);
            split_bf2(y10, y11, bh[nt][1], bl[nt][1]);
        }
#pragma unroll
        for (int mt = 0; mt < 4; mt++)
#pragma unroll
            for (int nt = 0; nt < 4; nt++) {
                mma_bf(Cf[mt][nt], ah[mt][0], ah[mt][1], ah[mt][2], ah[mt][3], bh[nt][0], bh[nt][1]);
                mma_bf(Cf[mt][nt], ah[mt][0], ah[mt][1], ah[mt][2], ah[mt][3], bl[nt][0], bl[nt][1]);
                mma_bf(Cf[mt][nt], al[mt][0], al[mt][1], al[mt][2], al[mt][3], bh[nt][0], bh[nt][1]);
            }

        cp_wait0();
        __syncthreads();
    }

    // epilogue
#pragma unroll
    for (int mt = 0; mt < 4; mt++) {
        int row0 = m0 + wm * 64 + mt * 16 + g;
#pragma unroll
        for (int nt = 0; nt < 4; nt++) {
            int col = n0 + wn * 32 + nt * 8 + 2 * j;
            float b0 = bias[col], b1 = bias[col + 1];
            float2 v0 = make_float2(Cf[mt][nt][0] + b0, Cf[mt][nt][1] + b1);
            float2 v1 = make_float2(Cf[mt][nt][2] + b0, Cf[mt][nt][3] + b1);
            if (MODE == 1) {
                *(float2*)(Cout + (size_t)row0 * DIMC + col) = v0;
                *(float2*)(Cout + (size_t)(row0 + 8) * DIMC + col) = v1;
            } else {
                int s = (col >= 2 * DIMC) ? 2 : (col >= DIMC ? 1 : 0);
                int rr = col - s * DIMC;
                int h = rr / HD;
                int d = rr - h * HD;
                float* base = (s == 0) ? g_q : (s == 1) ? g_k : g_v;
                int bb0 = row0 >> 11, t0 = row0 & (SEQ - 1);
                int r1 = row0 + 8;
                int bb1 = r1 >> 11, t1 = r1 & (SEQ - 1);
                *(float2*)(base + ((size_t)(bb0 * NH + h) * SEQ + t0) * HD + d) = v0;
                *(float2*)(base + ((size_t)(bb1 * NH + h) * SEQ + t1) * HD + d) = v1;
            }
        }
    }
}

// ---------------------------------------------------------------------------
// RoPE in place on g_q, g_k.
// ---------------------------------------------------------------------------
__global__ __launch_bounds__(256)
void rope_kernel()
{
    int idx = blockIdx.x * blockDim.x + threadIdx.x;
    int j = idx % 48;
    int rest = idx / 48;
    int t = rest & (SEQ - 1);
    int bh = rest >> 11;

    float freq = exp2f(-(2.f * j / 96.f) * 13.287712379549449f);
    float ang = (float)t * freq;
    float sn, cs;
    sincosf(ang, &sn, &cs);

    size_t base = ((size_t)bh * SEQ + t) * HD;
    float q1 = g_q[base + j], q2 = g_q[base + j + 48];
    g_q[base + j]      = q1 * cs - q2 * sn;
    g_q[base + j + 48] = q2 * cs + q1 * sn;
    float k1 = g_k[base + j], k2 = g_k[base + j + 48];
    g_k[base + j]      = k1 * cs - k2 * sn;
    g_k[base + j + 48] = k2 * cs + k1 * sn;
}

// ---------------------------------------------------------------------------
// Flash attention via mma.sync tf32.
// Block = (qtile 128, h, b), 256 threads = 8 warps; warp w owns Q rows w*16..+16.
// Q/K/V are pre-rounded to tf32 at SMEM-store time (no cvt in hot loops).
// ---------------------------------------------------------------------------
#define QLD 100
#define KLD 100
#define VLD 104
#define ATTN_SMEM ((128*QLD + 64*KLD + 64*VLD) * 4)   // 103424

__global__ __launch_bounds__(256, 1)
void attn_mma()
{
    extern __shared__ float smf[];
    float* Qs = smf;                        // [128][QLD]
    float* Ks = smf + 128 * QLD;            // [64][KLD]
    float* Vs = smf + 128 * QLD + 64 * KLD; // [64][VLD]

    int qt = blockIdx.x, h = blockIdx.y, b = blockIdx.z;
    int tid = threadIdx.x;
    int lane = tid & 31;
    int wid = tid >> 5;
    int g = lane >> 2, j = lane & 3;
    const float scale = rsqrtf((float)HD);

    const float* Qg = g_q + ((size_t)(b * NH + h) * SEQ + (size_t)qt * 128) * HD;
    const float* Kg = g_k + ((size_t)(b * NH + h) * SEQ) * HD;
    const float* Vg = g_v + ((size_t)(b * NH + h) * SEQ) * HD;

    // Load + prescale + tf32-round Q tile: 128 rows x 96 cols
    for (int f = tid; f < 128 * 24; f += 256) {
        int r = f / 24, c4 = (f % 24) * 4;
        float4 v = *(const float4*)(Qg + (size_t)r * HD + c4);
        v.x = __uint_as_float(f2tf(v.x * scale));
        v.y = __uint_as_float(f2tf(v.y * scale));
        v.z = __uint_as_float(f2tf(v.z * scale));
        v.w = __uint_as_float(f2tf(v.w * scale));
        *(float4*)(Qs + r * QLD + c4) = v;
    }

    float m0r = -1e30f, m1r = -1e30f, l0r = 0.f, l1r = 0.f;
    float O[12][4];
#pragma unroll
    for (int nt = 0; nt < 12; nt++)
#pragma unroll
        for (int r = 0; r < 4; r++) O[nt][r] = 0.f;

    int row0 = qt * 128 + wid * 16 + g;   // global query row of c0/c1
    int nkt = 2 * qt + 2;

    __syncthreads();

    for (int kt = 0; kt < nkt; kt++) {
        __syncthreads();   // previous iteration done reading Ks/Vs
        for (int f = tid; f < 64 * 24; f += 256) {
            int r = f / 24, c4 = (f % 24) * 4;
            float4 kv = *(const float4*)(Kg + ((size_t)kt * 64 + r) * HD + c4);
            float4 vv = *(const float4*)(Vg + ((size_t)kt * 64 + r) * HD + c4);
            kv.x = __uint_as_float(f2tf(kv.x)); kv.y = __uint_as_float(f2tf(kv.y));
            kv.z = __uint_as_float(f2tf(kv.z)); kv.w = __uint_as_float(f2tf(kv.w));
            vv.x = __uint_as_float(f2tf(vv.x)); vv.y = __uint_as_float(f2tf(vv.y));
            vv.z = __uint_as_float(f2tf(vv.z)); vv.w = __uint_as_float(f2tf(vv.w));
            *(float4*)(Ks + r * KLD + c4) = kv;
            *(float4*)(Vs + r * VLD + c4) = vv;
        }
        __syncthreads();

        // ---- S = Q @ K^T ----
        float S[8][4];
#pragma unroll
        for (int nt = 0; nt < 8; nt++)
#pragma unroll
            for (int r = 0; r < 4; r++) S[nt][r] = 0.f;

#pragma unroll
        for (int ks = 0; ks < 12; ks++) {
            int k0 = ks * 8;
            int qr = wid * 16 + g;
            uint32_t a0 = __float_as_uint(Qs[qr * QLD + k0 + j]);
            uint32_t a1 = __float_as_uint(Qs[(qr + 8) * QLD + k0 + j]);
            uint32_t a2 = __float_as_uint(Qs[qr * QLD + k0 + j + 4]);
            uint32_t a3 = __float_as_uint(Qs[(qr + 8) * QLD + k0 + j + 4]);
#pragma unroll
            for (int nt = 0; nt < 8; nt++) {
                uint32_t b0 = __float_as_uint(Ks[(nt * 8 + g) * KLD + k0 + j]);
                uint32_t b1 = __float_as_uint(Ks[(nt * 8 + g) * KLD + k0 + j + 4]);
                mma_tf(S[nt], a0, a1, a2, a3, b0, b1);
            }
        }

        // ---- causal mask (only possibly-clipped tiles) ----
        if (kt >= nkt - 2) {
            int colb = kt * 64;
#pragma unroll
            for (int nt = 0; nt < 8; nt++) {
                int c0 = colb + nt * 8 + 2 * j;
                if (c0 > row0)     S[nt][0] = -1e30f;
                if (c0 + 1 > row0) S[nt][1] = -1e30f;
                if (c0 > row0 + 8)     S[nt][2] = -1e30f;
                if (c0 + 1 > row0 + 8) S[nt][3] = -1e30f;
            }
        }

        // ---- online softmax ----
        float mx0 = -1e30f, mx1 = -1e30f;
#pragma unroll
        for (int nt = 0; nt < 8; nt++) {
            mx0 = fmaxf(mx0, fmaxf(S[nt][0], S[nt][1]));
            mx1 = fmaxf(mx1, fmaxf(S[nt][2], S[nt][3]));
        }
        mx0 = fmaxf(mx0, __shfl_xor_sync(0xffffffffu, mx0, 1));
        mx0 = fmaxf(mx0, __shfl_xor_sync(0xffffffffu, mx0, 2));
        mx1 = fmaxf(mx1, __shfl_xor_sync(0xffffffffu, mx1, 1));
        mx1 = fmaxf(mx1, __shfl_xor_sync(0xffffffffu, mx1, 2));

        float mn0 = fmaxf(m0r, mx0), mn1 = fmaxf(m1r, mx1);
        float al0 = __expf(m0r - mn0), al1 = __expf(m1r - mn1);
        float s0 = 0.f, s1 = 0.f;
#pragma unroll
        for (int nt = 0; nt < 8; nt++) {
            S[nt][0] = __expf(S[nt][0] - mn0);
            S[nt][1] = __expf(S[nt][1] - mn0);
            S[nt][2] = __expf(S[nt][2] - mn1);
            S[nt][3] = __expf(S[nt][3] - mn1);
            s0 += S[nt][0] + S[nt][1];
            s1 += S[nt][2] + S[nt][3];
        }
        s0 += __shfl_xor_sync(0xffffffffu, s0, 1);
        s0 += __shfl_xor_sync(0xffffffffu, s0, 2);
        s1 += __shfl_xor_sync(0xffffffffu, s1, 1);
        s1 += __shfl_xor_sync(0xffffffffu, s1, 2);
        l0r = l0r * al0 + s0;
        l1r = l1r * al1 + s1;
        m0r = mn0; m1r = mn1;
#pragma unroll
        for (int nt = 0; nt < 12; nt++) {
            O[nt][0] *= al0; O[nt][1] *= al0;
            O[nt][2] *= al1; O[nt][3] *= al1;
        }

        // ---- O += P @ V ----
        int src_lo = (lane & ~3) | (j >> 1);
        int par = j & 1;
#pragma unroll
        for (int ks = 0; ks < 8; ks++) {
            // relayout P (C-frag of tile ks) -> A-frag via shuffles
            float p00 = __shfl_sync(0xffffffffu, S[ks][0], src_lo);
            float p01 = __shfl_sync(0xffffffffu, S[ks][1], src_lo);
            float p10 = __shfl_sync(0xffffffffu, S[ks][0], src_lo + 2);
            float p11 = __shfl_sync(0xffffffffu, S[ks][1], src_lo + 2);
            float p20 = __shfl_sync(0xffffffffu, S[ks][2], src_lo);
            float p21 = __shfl_sync(0xffffffffu, S[ks][3], src_lo);
            float p30 = __shfl_sync(0xffffffffu, S[ks][2], src_lo + 2);
            float p31 = __shfl_sync(0xffffffffu, S[ks][3], src_lo + 2);
            uint32_t a0 = f2tf(par ? p01 : p00);   // (row g,   col j)
            uint32_t a1 = f2tf(par ? p21 : p20);   // (row g+8, col j)
            uint32_t a2 = f2tf(par ? p11 : p10);   // (row g,   col j+4)
            uint32_t a3 = f2tf(par ? p31 : p30);   // (row g+8, col j+4)
#pragma unroll
            for (int nt = 0; nt < 12; nt++) {
                uint32_t b0 = __float_as_uint(Vs[(ks * 8 + j) * VLD + nt * 8 + g]);
                uint32_t b1 = __float_as_uint(Vs[(ks * 8 + j + 4) * VLD + nt * 8 + g]);
                mma_tf(O[nt], a0, a1, a2, a3, b0, b1);
            }
        }
    }

    // ---- writeback O / l -> g_att [B,T,768] ----
    float inv0 = 1.f / l0r, inv1 = 1.f / l1r;
    float* outb = g_att + ((size_t)b * SEQ + row0) * DIMC + h * HD;
#pragma unroll
    for (int nt = 0; nt < 12; nt++) {
        int d = nt * 8 + 2 * j;
        *(float2*)(outb + d) = make_float2(O[nt][0] * inv0, O[nt][1] * inv0);
        *(float2*)(outb + (size_t)8 * DIMC + d) = make_float2(O[nt][2] * inv1, O[nt][3] * inv1);
    }
}

// ---------------------------------------------------------------------------
// Launch
// Inputs: 0=x, 1=mask (ignored, causal), 2=w_qkv, 3=b_qkv, 4=w_proj, 5=b_proj
// ---------------------------------------------------------------------------
extern "C" void kernel_launch(void* const* d_in, const int* in_sizes, int n_in,
                              void* d_out, int out_size)
{
    const float* x      = (const float*)d_in[0];
    const float* w_qkv  = (const float*)d_in[2];
    const float* b_qkv  = (const float*)d_in[3];
    const float* w_proj = (const float*)d_in[4];
    const float* b_proj = (const float*)d_in[5];
    float* out = (float*)d_out;

    cudaFuncSetAttribute(attn_mma, cudaFuncAttributeMaxDynamicSharedMemorySize,
                         ATTN_SMEM);

    // QKV: M=8192, N=2304
    gemm_mma<0><<<dim3(2304 / 128, MTOT / 128), 256>>>(x, w_qkv, b_qkv, nullptr);

    // RoPE
    rope_kernel<<<(BATCH * NH * SEQ * 48) / 256, 256>>>();

    // Attention
    attn_mma<<<dim3(SEQ / 128, NH, BATCH), 256, ATTN_SMEM>>>();

    // Projection: M=8192, N=768
    gemm_mma<1><<<dim3(DIMC / 128, MTOT / 128), 256>>>(nullptr, w_proj, b_proj, out);
}

// round 5
// speedup vs baseline: 2.9532x; 1.5206x over previous
#include <cuda_runtime.h>
#include <math.h>
#include <stdint.h>

#define DIMC 768
#define NH 8
#define HD 96
#define BATCH 4
#define SEQ 2048
#define MTOT (BATCH*SEQ)

// Scratch (static device arrays; no cudaMalloc allowed)
__device__ float g_q[(size_t)BATCH*NH*SEQ*HD];
__device__ float g_k[(size_t)BATCH*NH*SEQ*HD];
__device__ float g_v[(size_t)BATCH*NH*SEQ*HD];
__device__ float g_att[(size_t)MTOT*DIMC];

// ---------------------------------------------------------------------------
// helpers
// ---------------------------------------------------------------------------
__device__ __forceinline__ uint32_t smem_u32(const void* p) {
    uint32_t a;
    asm("{ .reg .u64 t; cvta.to.shared.u64 t, %1; cvt.u32.u64 %0, t; }" : "=r"(a) : "l"(p));
    return a;
}
__device__ __forceinline__ void cp16(uint32_t s, const float* g) {
    asm volatile("cp.async.ca.shared.global [%0], [%1], 16;" :: "r"(s), "l"(g) : "memory");
}
__device__ __forceinline__ void cp_commit() {
    asm volatile("cp.async.commit_group;" ::: "memory");
}
__device__ __forceinline__ void cp_wait1() {
    asm volatile("cp.async.wait_group 1;" ::: "memory");
}
__device__ __forceinline__ uint32_t f2tf(float x) {
    uint32_t r;
    asm("cvt.rna.tf32.f32 %0, %1;" : "=r"(r) : "f"(x));
    return r;
}
// pack two f32 -> bf16x2 (x0 -> low half, x1 -> high half)
__device__ __forceinline__ uint32_t pack_bf2(float x0, float x1) {
    uint32_t r;
    asm("cvt.rn.bf16x2.f32 %0, %1, %2;" : "=r"(r) : "f"(x1), "f"(x0));
    return r;
}
__device__ __forceinline__ void split_bf2(float x0, float x1, uint32_t& hi, uint32_t& lo) {
    hi = pack_bf2(x0, x1);
    float h0 = __uint_as_float(hi << 16);
    float h1 = __uint_as_float(hi & 0xffff0000u);
    lo = pack_bf2(x0 - h0, x1 - h1);
}
// D += A(16x8) * B(8x8), tf32 inputs, f32 accum
__device__ __forceinline__ void mma_tf(float d[4], uint32_t a0, uint32_t a1,
                                       uint32_t a2, uint32_t a3,
                                       uint32_t b0, uint32_t b1) {
    asm volatile(
        "mma.sync.aligned.m16n8k8.row.col.f32.tf32.tf32.f32 "
        "{%0,%1,%2,%3},{%4,%5,%6,%7},{%8,%9},{%0,%1,%2,%3};"
        : "+f"(d[0]), "+f"(d[1]), "+f"(d[2]), "+f"(d[3])
        : "r"(a0), "r"(a1), "r"(a2), "r"(a3), "r"(b0), "r"(b1));
}
// D += A(16x16) * B(16x8), bf16 inputs, f32 accum
__device__ __forceinline__ void mma_bf(float d[4], uint32_t a0, uint32_t a1,
                                       uint32_t a2, uint32_t a3,
                                       uint32_t b0, uint32_t b1) {
    asm volatile(
        "mma.sync.aligned.m16n8k16.row.col.f32.bf16.bf16.f32 "
        "{%0,%1,%2,%3},{%4,%5,%6,%7},{%8,%9},{%0,%1,%2,%3};"
        : "+f"(d[0]), "+f"(d[1]), "+f"(d[2]), "+f"(d[3])
        : "r"(a0), "r"(a1), "r"(a2), "r"(a3), "r"(b0), "r"(b1));
}

// ---------------------------------------------------------------------------
// GEMM v2: bf16 hi/lo split, pre-packed SMEM, 512 threads, BK=32.
// C[M,N] = A[M,768] @ W[N,768]^T + bias
// Warp grid 4(m) x 4(n), warp tile 32x32. One __syncthreads per BK=32.
// MODE 0: A = x, scatter epilogue into g_q/g_k/g_v. MODE 1: A = g_att -> C.
// ---------------------------------------------------------------------------
#define GLD 20                      // padded word stride (16 k-words + 4)
#define GSW (128*GLD)               // words per (matrix-part, stage)
#define GEMM_SMEM_BYTES (8*GSW*4)   // Ah/Al/Wh/Wl x 2 stages = 81920 B

template<int MODE>
__global__ __launch_bounds__(512, 1)
void gemm_mma(const float* __restrict__ Ain, const float* __restrict__ W,
              const float* __restrict__ bias, float* __restrict__ Cout)
{
    extern __shared__ uint32_t smw[];
    // layout (word offsets): Ah: st*GSW, Al: 2*GSW+st*GSW, Wh: 4*GSW+st, Wl: 6*GSW+st

    const float* A = (MODE == 1) ? (const float*)g_att : Ain;

    int tid = threadIdx.x;
    int lane = tid & 31;
    int wid = tid >> 5;               // 0..15
    int g = lane >> 2, j = lane & 3;
    int wm = wid & 3, wn = wid >> 2;  // 4 x 4 warp grid
    int m0 = blockIdx.y * 128;
    int n0 = blockIdx.x * 128;

    // loader mapping: 512 threads cover 128 rows x 32 floats per matrix
    int lrow = tid >> 2;
    int lcf = (tid & 3) * 8;          // float col: 0,8,16,24
    int lcw = (tid & 3) * 4;          // word col

    float Cf[2][4][4];
#pragma unroll
    for (int mt = 0; mt < 2; mt++)
#pragma unroll
        for (int nt = 0; nt < 4; nt++)
#pragma unroll
            for (int r = 0; r < 4; r++) Cf[mt][nt][r] = 0.f;

    float4 ra0, ra1, rw0, rw1;
    auto ldg = [&](int c) {
        const float* ap = A + (size_t)(m0 + lrow) * DIMC + c * 32 + lcf;
        const float* wp = W + (size_t)(n0 + lrow) * DIMC + c * 32 + lcf;
        ra0 = *(const float4*)ap;       ra1 = *(const float4*)(ap + 4);
        rw0 = *(const float4*)wp;       rw1 = *(const float4*)(wp + 4);
    };
    auto sts = [&](int st) {
        uint32_t h0, h1, h2, h3, l0, l1, l2, l3;
        split_bf2(ra0.x, ra0.y, h0, l0); split_bf2(ra0.z, ra0.w, h1, l1);
        split_bf2(ra1.x, ra1.y, h2, l2); split_bf2(ra1.z, ra1.w, h3, l3);
        int off = lrow * GLD + lcw;
        *(uint4*)(smw + st * GSW + off)           = make_uint4(h0, h1, h2, h3);
        *(uint4*)(smw + 2 * GSW + st * GSW + off) = make_uint4(l0, l1, l2, l3);
        split_bf2(rw0.x, rw0.y, h0, l0); split_bf2(rw0.z, rw0.w, h1, l1);
        split_bf2(rw1.x, rw1.y, h2, l2); split_bf2(rw1.z, rw1.w, h3, l3);
        *(uint4*)(smw + 4 * GSW + st * GSW + off) = make_uint4(h0, h1, h2, h3);
        *(uint4*)(smw + 6 * GSW + st * GSW + off) = make_uint4(l0, l1, l2, l3);
    };

    ldg(0);
    sts(0);
    __syncthreads();

    const int NC = DIMC / 32;   // 24
    for (int c = 0; c < NC; c++) {
        int buf = c & 1;
        if (c + 1 < NC) ldg(c + 1);

        const uint32_t* Ah = smw + buf * GSW;
        const uint32_t* Al = smw + 2 * GSW + buf * GSW;
        const uint32_t* Wh = smw + 4 * GSW + buf * GSW;
        const uint32_t* Wl = smw + 6 * GSW + buf * GSW;

#pragma unroll
        for (int s = 0; s < 2; s++) {
            uint32_t ah[2][4], al[2][4];
#pragma unroll
            for (int mt = 0; mt < 2; mt++) {
                int r = wm * 32 + mt * 16 + g;
                int o0 = r * GLD + s * 8 + j;
                int o1 = (r + 8) * GLD + s * 8 + j;
                ah[mt][0] = Ah[o0];     ah[mt][1] = Ah[o1];
                ah[mt][2] = Ah[o0 + 4]; ah[mt][3] = Ah[o1 + 4];
                al[mt][0] = Al[o0];     al[mt][1] = Al[o1];
                al[mt][2] = Al[o0 + 4]; al[mt][3] = Al[o1 + 4];
            }
            uint32_t bh[4][2], bl[4][2];
#pragma unroll
            for (int nt = 0; nt < 4; nt++) {
                int rn = wn * 32 + nt * 8 + g;
                int o = rn * GLD + s * 8 + j;
                bh[nt][0] = Wh[o]; bh[nt][1] = Wh[o + 4];
                bl[nt][0] = Wl[o]; bl[nt][1] = Wl[o + 4];
            }
#pragma unroll
            for (int mt = 0; mt < 2; mt++)
#pragma unroll
                for (int nt = 0; nt < 4; nt++) {
                    mma_bf(Cf[mt][nt], ah[mt][0], ah[mt][1], ah[mt][2], ah[mt][3], bh[nt][0], bh[nt][1]);
                    mma_bf(Cf[mt][nt], ah[mt][0], ah[mt][1], ah[mt][2], ah[mt][3], bl[nt][0], bl[nt][1]);
                    mma_bf(Cf[mt][nt], al[mt][0], al[mt][1], al[mt][2], al[mt][3], bh[nt][0], bh[nt][1]);
                }
        }

        if (c + 1 < NC) sts(buf ^ 1);
        __syncthreads();
    }

    // epilogue
#pragma unroll
    for (int mt = 0; mt < 2; mt++) {
        int row0 = m0 + wm * 32 + mt * 16 + g;
#pragma unroll
        for (int nt = 0; nt < 4; nt++) {
            int col = n0 + wn * 32 + nt * 8 + 2 * j;
            float b0 = bias[col], b1 = bias[col + 1];
            float2 v0 = make_float2(Cf[mt][nt][0] + b0, Cf[mt][nt][1] + b1);
            float2 v1 = make_float2(Cf[mt][nt][2] + b0, Cf[mt][nt][3] + b1);
            if (MODE == 1) {
                *(float2*)(Cout + (size_t)row0 * DIMC + col) = v0;
                *(float2*)(Cout + (size_t)(row0 + 8) * DIMC + col) = v1;
            } else {
                int s = (col >= 2 * DIMC) ? 2 : (col >= DIMC ? 1 : 0);
                int rr = col - s * DIMC;
                int h = rr / HD;
                int d = rr - h * HD;
                float* base = (s == 0) ? g_q : (s == 1) ? g_k : g_v;
                int bb0 = row0 >> 11, t0 = row0 & (SEQ - 1);
                int r1 = row0 + 8;
                int bb1 = r1 >> 11, t1 = r1 & (SEQ - 1);
                *(float2*)(base + ((size_t)(bb0 * NH + h) * SEQ + t0) * HD + d) = v0;
                *(float2*)(base + ((size_t)(bb1 * NH + h) * SEQ + t1) * HD + d) = v1;
            }
        }
    }
}

// ---------------------------------------------------------------------------
// RoPE in place on g_q, g_k.
// ---------------------------------------------------------------------------
__global__ __launch_bounds__(256)
void rope_kernel()
{
    int idx = blockIdx.x * blockDim.x + threadIdx.x;
    int j = idx % 48;
    int rest = idx / 48;
    int t = rest & (SEQ - 1);
    int bh = rest >> 11;

    float freq = exp2f(-(2.f * j / 96.f) * 13.287712379549449f);
    float ang = (float)t * freq;
    float sn, cs;
    sincosf(ang, &sn, &cs);

    size_t base = ((size_t)bh * SEQ + t) * HD;
    float q1 = g_q[base + j], q2 = g_q[base + j + 48];
    g_q[base + j]      = q1 * cs - q2 * sn;
    g_q[base + j + 48] = q2 * cs + q1 * sn;
    float k1 = g_k[base + j], k2 = g_k[base + j + 48];
    g_k[base + j]      = k1 * cs - k2 * sn;
    g_k[base + j + 48] = k2 * cs + k1 * sn;
}

// ---------------------------------------------------------------------------
// Flash attention via mma.sync tf32, 3-stage cp.async K/V ring.
// Block = (qtile 128, h, b), 256 threads = 8 warps; warp w owns Q rows w*16..+16.
// K/V consumed as raw f32 bits (HW tf32 truncation). One sync per K-tile.
// ---------------------------------------------------------------------------
#define QLD 100
#define KLD 100
#define VLD 104
#define KVSTG (64*(KLD+VLD))
#define ATTN_SMEM ((128*QLD + 3*KVSTG) * 4)   // 207872

__global__ __launch_bounds__(256, 1)
void attn_mma()
{
    extern __shared__ float smf[];
    float* Qs = smf;                  // [128][QLD]
    float* KV = smf + 128 * QLD;      // 3 stages of K[64][KLD] + V[64][VLD]

    int qt = gridDim.x - 1 - blockIdx.x;   // longest blocks first
    int h = blockIdx.y, b = blockIdx.z;
    int tid = threadIdx.x;
    int lane = tid & 31;
    int wid = tid >> 5;
    int g = lane >> 2, j = lane & 3;
    const float scale = rsqrtf((float)HD);

    const float* Qg = g_q + ((size_t)(b * NH + h) * SEQ + (size_t)qt * 128) * HD;
    const float* Kg = g_k + ((size_t)(b * NH + h) * SEQ) * HD;
    const float* Vg = g_v + ((size_t)(b * NH + h) * SEQ) * HD;

    int nkt = 2 * qt + 2;

    auto issue_kv = [&](int kt) {
        int st = kt % 3;
        float* Ks = KV + st * KVSTG;
        float* Vs = Ks + 64 * KLD;
        const float* kp = Kg + (size_t)kt * 64 * HD;
        const float* vp = Vg + (size_t)kt * 64 * HD;
#pragma unroll
        for (int it = 0; it < 6; it++) {
            int f = tid + it * 256;
            int r = f / 24, c4 = (f % 24) * 4;
            cp16(smem_u32(Ks + r * KLD + c4), kp + (size_t)r * HD + c4);
            cp16(smem_u32(Vs + r * VLD + c4), vp + (size_t)r * HD + c4);
        }
    };

    // prologue: prefetch stages 0,1 ; load+scale+round Q
    issue_kv(0); cp_commit();
    issue_kv(1); cp_commit();

    for (int f = tid; f < 128 * 24; f += 256) {
        int r = f / 24, c4 = (f % 24) * 4;
        float4 v = *(const float4*)(Qg + (size_t)r * HD + c4);
        v.x = __uint_as_float(f2tf(v.x * scale));
        v.y = __uint_as_float(f2tf(v.y * scale));
        v.z = __uint_as_float(f2tf(v.z * scale));
        v.w = __uint_as_float(f2tf(v.w * scale));
        *(float4*)(Qs + r * QLD + c4) = v;
    }

    float m0r = -1e30f, m1r = -1e30f, l0r = 0.f, l1r = 0.f;
    float O[12][4];
#pragma unroll
    for (int nt = 0; nt < 12; nt++)
#pragma unroll
        for (int r = 0; r < 4; r++) O[nt][r] = 0.f;

    int row0 = qt * 128 + wid * 16 + g;

    for (int kt = 0; kt < nkt; kt++) {
        cp_wait1();          // group kt complete (in-order)
        __syncthreads();     // stage kt visible to all; all done with kt-1
        if (kt + 2 < nkt) issue_kv(kt + 2);
        cp_commit();         // (possibly empty group keeps ordering simple)

        int st = kt % 3;
        const float* Ks = KV + st * KVSTG;
        const float* Vs = Ks + 64 * KLD;

        // ---- S = Q @ K^T ----
        float S[8][4];
#pragma unroll
        for (int nt = 0; nt < 8; nt++)
#pragma unroll
            for (int r = 0; r < 4; r++) S[nt][r] = 0.f;

#pragma unroll
        for (int ks = 0; ks < 12; ks++) {
            int k0 = ks * 8;
            int qr = wid * 16 + g;
            uint32_t a0 = __float_as_uint(Qs[qr * QLD + k0 + j]);
            uint32_t a1 = __float_as_uint(Qs[(qr + 8) * QLD + k0 + j]);
            uint32_t a2 = __float_as_uint(Qs[qr * QLD + k0 + j + 4]);
            uint32_t a3 = __float_as_uint(Qs[(qr + 8) * QLD + k0 + j + 4]);
#pragma unroll
            for (int nt = 0; nt < 8; nt++) {
                uint32_t b0 = __float_as_uint(Ks[(nt * 8 + g) * KLD + k0 + j]);
                uint32_t b1 = __float_as_uint(Ks[(nt * 8 + g) * KLD + k0 + j + 4]);
                mma_tf(S[nt], a0, a1, a2, a3, b0, b1);
            }
        }

        // ---- causal mask (only possibly-clipped tiles) ----
        if (kt >= nkt - 2) {
            int colb = kt * 64;
#pragma unroll
            for (int nt = 0; nt < 8; nt++) {
                int c0 = colb + nt * 8 + 2 * j;
                if (c0 > row0)     S[nt][0] = -1e30f;
                if (c0 + 1 > row0) S[nt][1] = -1e30f;
                if (c0 > row0 + 8)     S[nt][2] = -1e30f;
                if (c0 + 1 > row0 + 8) S[nt][3] = -1e30f;
            }
        }

        // ---- online softmax ----
        float mx0 = -1e30f, mx1 = -1e30f;
#pragma unroll
        for (int nt = 0; nt < 8; nt++) {
            mx0 = fmaxf(mx0, fmaxf(S[nt][0], S[nt][1]));
            mx1 = fmaxf(mx1, fmaxf(S[nt][2], S[nt][3]));
        }
        mx0 = fmaxf(mx0, __shfl_xor_sync(0xffffffffu, mx0, 1));
        mx0 = fmaxf(mx0, __shfl_xor_sync(0xffffffffu, mx0, 2));
        mx1 = fmaxf(mx1, __shfl_xor_sync(0xffffffffu, mx1, 1));
        mx1 = fmaxf(mx1, __shfl_xor_sync(0xffffffffu, mx1, 2));

        float mn0 = fmaxf(m0r, mx0), mn1 = fmaxf(m1r, mx1);
        float al0 = __expf(m0r - mn0), al1 = __expf(m1r - mn1);
        float s0 = 0.f, s1 = 0.f;
#pragma unroll
        for (int nt = 0; nt < 8; nt++) {
            S[nt][0] = __expf(S[nt][0] - mn0);
            S[nt][1] = __expf(S[nt][1] - mn0);
            S[nt][2] = __expf(S[nt][2] - mn1);
            S[nt][3] = __expf(S[nt][3] - mn1);
            s0 += S[nt][0] + S[nt][1];
            s1 += S[nt][2] + S[nt][3];
        }
        s0 += __shfl_xor_sync(0xffffffffu, s0, 1);
        s0 += __shfl_xor_sync(0xffffffffu, s0, 2);
        s1 += __shfl_xor_sync(0xffffffffu, s1, 1);
        s1 += __shfl_xor_sync(0xffffffffu, s1, 2);
        l0r = l0r * al0 + s0;
        l1r = l1r * al1 + s1;
        m0r = mn0; m1r = mn1;
#pragma unroll
        for (int nt = 0; nt < 12; nt++) {
            O[nt][0] *= al0; O[nt][1] *= al0;
            O[nt][2] *= al1; O[nt][3] *= al1;
        }

        // ---- O += P @ V ----
        int src_lo = (lane & ~3) | (j >> 1);
        int par = j & 1;
#pragma unroll
        for (int ks = 0; ks < 8; ks++) {
            float p00 = __shfl_sync(0xffffffffu, S[ks][0], src_lo);
            float p01 = __shfl_sync(0xffffffffu, S[ks][1], src_lo);
            float p10 = __shfl_sync(0xffffffffu, S[ks][0], src_lo + 2);
            float p11 = __shfl_sync(0xffffffffu, S[ks][1], src_lo + 2);
            float p20 = __shfl_sync(0xffffffffu, S[ks][2], src_lo);
            float p21 = __shfl_sync(0xffffffffu, S[ks][3], src_lo);
            float p30 = __shfl_sync(0xffffffffu, S[ks][2], src_lo + 2);
            float p31 = __shfl_sync(0xffffffffu, S[ks][3], src_lo + 2);
            uint32_t a0 = f2tf(par ? p01 : p00);
            uint32_t a1 = f2tf(par ? p21 : p20);
            uint32_t a2 = f2tf(par ? p11 : p10);
            uint32_t a3 = f2tf(par ? p31 : p30);
#pragma unroll
            for (int nt = 0; nt < 12; nt++) {
                uint32_t b0 = __float_as_uint(Vs[(ks * 8 + j) * VLD + nt * 8 + g]);
                uint32_t b1 = __float_as_uint(Vs[(ks * 8 + j + 4) * VLD + nt * 8 + g]);
                mma_tf(O[nt], a0, a1, a2, a3, b0, b1);
            }
        }
        __syncthreads();   // all warps done with stage kt before it is re-filled
    }

    // ---- writeback O / l -> g_att [B,T,768] ----
    float inv0 = 1.f / l0r, inv1 = 1.f / l1r;
    float* outb = g_att + ((size_t)b * SEQ + row0) * DIMC + h * HD;
#pragma unroll
    for (int nt = 0; nt < 12; nt++) {
        int d = nt * 8 + 2 * j;
        *(float2*)(outb + d) = make_float2(O[nt][0] * inv0, O[nt][1] * inv0);
        *(float2*)(outb + (size_t)8 * DIMC + d) = make_float2(O[nt][2] * inv1, O[nt][3] * inv1);
    }
}

// ---------------------------------------------------------------------------
// Launch
// Inputs: 0=x, 1=mask (ignored, causal), 2=w_qkv, 3=b_qkv, 4=w_proj, 5=b_proj
// ---------------------------------------------------------------------------
extern "C" void kernel_launch(void* const* d_in, const int* in_sizes, int n_in,
                              void* d_out, int out_size)
{
    const float* x      = (const float*)d_in[0];
    const float* w_qkv  = (const float*)d_in[2];
    const float* b_qkv  = (const float*)d_in[3];
    const float* w_proj = (const float*)d_in[4];
    const float* b_proj = (const float*)d_in[5];
    float* out = (float*)d_out;

    cudaFuncSetAttribute(attn_mma, cudaFuncAttributeMaxDynamicSharedMemorySize,
                         ATTN_SMEM);
    cudaFuncSetAttribute(gemm_mma<0>, cudaFuncAttributeMaxDynamicSharedMemorySize,
                         GEMM_SMEM_BYTES);
    cudaFuncSetAttribute(gemm_mma<1>, cudaFuncAttributeMaxDynamicSharedMemorySize,
                         GEMM_SMEM_BYTES);

    // QKV: M=8192, N=2304
    gemm_mma<0><<<dim3(2304 / 128, MTOT / 128), 512, GEMM_SMEM_BYTES>>>(x, w_qkv, b_qkv, nullptr);

    // RoPE
    rope_kernel<<<(BATCH * NH * SEQ * 48) / 256, 256>>>();

    // Attention
    attn_mma<<<dim3(SEQ / 128, NH, BATCH), 256, ATTN_SMEM>>>();

    // Projection: M=8192, N=768
    gemm_mma<1><<<dim3(DIMC / 128, MTOT / 128), 512, GEMM_SMEM_BYTES>>>(nullptr, w_proj, b_proj, out);
}

// round 6
// speedup vs baseline: 2.9670x; 1.0047x over previous
#include <cuda_runtime.h>
#include <math.h>
#include <stdint.h>

#define DIMC 768
#define KW (DIMC/2)          // 384 words per row (bf16x2)
#define NH 8
#define HD 96
#define BATCH 4
#define SEQ 2048
#define MTOT (BATCH*SEQ)

// Scratch (static device arrays; no cudaMalloc allowed)
__device__ float g_q[(size_t)BATCH*NH*SEQ*HD];
__device__ float g_k[(size_t)BATCH*NH*SEQ*HD];
__device__ float g_v[(size_t)BATCH*NH*SEQ*HD];
// packed bf16 hi/lo operand arrays
__device__ uint32_t g_xh[(size_t)MTOT*KW],  g_xl[(size_t)MTOT*KW];
__device__ uint32_t g_wqh[(size_t)3*DIMC*KW], g_wql[(size_t)3*DIMC*KW];
__device__ uint32_t g_wph[(size_t)DIMC*KW],  g_wpl[(size_t)DIMC*KW];
__device__ uint32_t g_atth[(size_t)MTOT*KW], g_attl[(size_t)MTOT*KW];

// ---------------------------------------------------------------------------
// helpers
// ---------------------------------------------------------------------------
__device__ __forceinline__ uint32_t smem_u32(const void* p) {
    uint32_t a;
    asm("{ .reg .u64 t; cvta.to.shared.u64 t, %1; cvt.u32.u64 %0, t; }" : "=r"(a) : "l"(p));
    return a;
}
__device__ __forceinline__ void cp16(uint32_t s, const void* g) {
    asm volatile("cp.async.ca.shared.global [%0], [%1], 16;" :: "r"(s), "l"(g) : "memory");
}
__device__ __forceinline__ void cp_commit() {
    asm volatile("cp.async.commit_group;" ::: "memory");
}
__device__ __forceinline__ void cp_wait1() {
    asm volatile("cp.async.wait_group 1;" ::: "memory");
}
__device__ __forceinline__ uint32_t f2tf(float x) {
    uint32_t r;
    asm("cvt.rna.tf32.f32 %0, %1;" : "=r"(r) : "f"(x));
    return r;
}
__device__ __forceinline__ uint32_t pack_bf2(float x0, float x1) {
    uint32_t r;
    asm("cvt.rn.bf16x2.f32 %0, %1, %2;" : "=r"(r) : "f"(x1), "f"(x0));
    return r;
}
__device__ __forceinline__ void split_bf2(float x0, float x1, uint32_t& hi, uint32_t& lo) {
    hi = pack_bf2(x0, x1);
    float h0 = __uint_as_float(hi << 16);
    float h1 = __uint_as_float(hi & 0xffff0000u);
    lo = pack_bf2(x0 - h0, x1 - h1);
}
__device__ __forceinline__ void ldsm4(uint32_t& r0, uint32_t& r1, uint32_t& r2,
                                      uint32_t& r3, uint32_t addr) {
    asm volatile("ldmatrix.sync.aligned.m8n8.x4.shared.b16 {%0,%1,%2,%3}, [%4];"
                 : "=r"(r0), "=r"(r1), "=r"(r2), "=r"(r3) : "r"(addr));
}
__device__ __forceinline__ void mma_tf(float d[4], uint32_t a0, uint32_t a1,
                                       uint32_t a2, uint32_t a3,
                                       uint32_t b0, uint32_t b1) {
    asm volatile(
        "mma.sync.aligned.m16n8k8.row.col.f32.tf32.tf32.f32 "
        "{%0,%1,%2,%3},{%4,%5,%6,%7},{%8,%9},{%0,%1,%2,%3};"
        : "+f"(d[0]), "+f"(d[1]), "+f"(d[2]), "+f"(d[3])
        : "r"(a0), "r"(a1), "r"(a2), "r"(a3), "r"(b0), "r"(b1));
}
__device__ __forceinline__ void mma_bf(float d[4], uint32_t a0, uint32_t a1,
                                       uint32_t a2, uint32_t a3,
                                       uint32_t b0, uint32_t b1) {
    asm volatile(
        "mma.sync.aligned.m16n8k16.row.col.f32.bf16.bf16.f32 "
        "{%0,%1,%2,%3},{%4,%5,%6,%7},{%8,%9},{%0,%1,%2,%3};"
        : "+f"(d[0]), "+f"(d[1]), "+f"(d[2]), "+f"(d[3])
        : "r"(a0), "r"(a1), "r"(a2), "r"(a3), "r"(b0), "r"(b1));
}

// ---------------------------------------------------------------------------
// pack: f32 array -> (hi bf16x2, lo bf16x2) word arrays
// ---------------------------------------------------------------------------
__global__ __launch_bounds__(256)
void pack_kernel(const float* __restrict__ src, uint32_t* __restrict__ hi,
                 uint32_t* __restrict__ lo, int nwords)
{
    int i = blockIdx.x * blockDim.x + threadIdx.x;
    if (i < nwords) {
        float2 v = ((const float2*)src)[i];
        uint32_t h, l;
        split_bf2(v.x, v.y, h, l);
        hi[i] = h; lo[i] = l;
    }
}

// ---------------------------------------------------------------------------
// GEMM v3: packed bf16 hi/lo inputs, ldmatrix fragments, 3-stage cp.async ring.
// C[M,N] = A[M,768] @ W[N,768]^T + bias ; 512 threads, 4x4 warps, tile 128x128.
// MODE 0: scatter into g_q/g_k/g_v. MODE 1: write Cout.
// ---------------------------------------------------------------------------
#define GLDW 20                    // padded word stride per row (16 + 4)
#define TSZ (128*GLDW)             // words per (array, stage)
#define GEMM_SMEM_BYTES (3*4*TSZ*4)   // 3 stages x {Ah,Al,Wh,Wl} = 122880

template<int MODE>
__global__ __launch_bounds__(512, 1)
void gemm_mma(const uint32_t* __restrict__ Ah_g, const uint32_t* __restrict__ Al_g,
              const uint32_t* __restrict__ Wh_g, const uint32_t* __restrict__ Wl_g,
              const float* __restrict__ bias, float* __restrict__ Cout)
{
    extern __shared__ uint32_t smw[];

    int tid = threadIdx.x;
    int lane = tid & 31;
    int wid = tid >> 5;
    int g = lane >> 2, j = lane & 3;
    int wm = wid & 3, wn = wid >> 2;
    int m0 = blockIdx.y * 128;
    int n0 = blockIdx.x * 128;

    // loader mapping: thread -> (row, 16B chunk), one cp16 per array
    int lrow = tid >> 2;
    int lcw = (tid & 3) * 4;

    const uint32_t* srcA_h = Ah_g + (size_t)(m0 + lrow) * KW + lcw;
    const uint32_t* srcA_l = Al_g + (size_t)(m0 + lrow) * KW + lcw;
    const uint32_t* srcW_h = Wh_g + (size_t)(n0 + lrow) * KW + lcw;
    const uint32_t* srcW_l = Wl_g + (size_t)(n0 + lrow) * KW + lcw;
    uint32_t dst_off = smem_u32(smw) + (uint32_t)(lrow * GLDW + lcw) * 4;

    auto issue = [&](int c) {
        uint32_t sb = dst_off + (uint32_t)((c % 3) * 4 * TSZ) * 4;
        int ko = c * 16;
        cp16(sb,                      srcA_h + ko);
        cp16(sb + (uint32_t)TSZ * 4,  srcA_l + ko);
        cp16(sb + (uint32_t)2*TSZ*4,  srcW_h + ko);
        cp16(sb + (uint32_t)3*TSZ*4,  srcW_l + ko);
    };

    // per-warp ldmatrix base offsets (within a stage's array)
    uint32_t smbase = smem_u32(smw);
    int arowA = wm * 32 + (lane & 15);           // + mt*16
    int acolA = ((lane >> 4) & 1) * 4;           // + s*8
    int arowB = wn * 32 + (lane & 7) + ((lane >> 4) & 1) * 8;   // + p*16
    int acolB = ((lane >> 3) & 1) * 4;           // + s*8

    float Cf[2][4][4];
#pragma unroll
    for (int mt = 0; mt < 2; mt++)
#pragma unroll
        for (int nt = 0; nt < 4; nt++)
#pragma unroll
            for (int r = 0; r < 4; r++) Cf[mt][nt][r] = 0.f;

    issue(0); cp_commit();
    issue(1); cp_commit();

    const int NC = DIMC / 32;   // 24
    for (int c = 0; c < NC; c++) {
        cp_wait1();
        __syncthreads();
        if (c + 2 < NC) issue(c + 2);
        cp_commit();

        uint32_t stb = smbase + (uint32_t)((c % 3) * 4 * TSZ) * 4;
        uint32_t sAh = stb, sAl = stb + TSZ * 4;
        uint32_t sWh = stb + 2 * TSZ * 4, sWl = stb + 3 * TSZ * 4;

#pragma unroll
        for (int s = 0; s < 2; s++) {
            uint32_t ah[2][4], al[2][4], bh[4][2], bl[4][2];
#pragma unroll
            for (int mt = 0; mt < 2; mt++) {
                uint32_t off = (uint32_t)((arowA + mt * 16) * GLDW + s * 8 + acolA) * 4;
                ldsm4(ah[mt][0], ah[mt][1], ah[mt][2], ah[mt][3], sAh + off);
                ldsm4(al[mt][0], al[mt][1], al[mt][2], al[mt][3], sAl + off);
            }
#pragma unroll
            for (int p = 0; p < 2; p++) {
                uint32_t off = (uint32_t)((arowB + p * 16) * GLDW + s * 8 + acolB) * 4;
                ldsm4(bh[2*p][0], bh[2*p][1], bh[2*p+1][0], bh[2*p+1][1], sWh + off);
                ldsm4(bl[2*p][0], bl[2*p][1], bl[2*p+1][0], bl[2*p+1][1], sWl + off);
            }
#pragma unroll
            for (int mt = 0; mt < 2; mt++)
#pragma unroll
                for (int nt = 0; nt < 4; nt++) {
                    mma_bf(Cf[mt][nt], ah[mt][0], ah[mt][1], ah[mt][2], ah[mt][3], bh[nt][0], bh[nt][1]);
                    mma_bf(Cf[mt][nt], ah[mt][0], ah[mt][1], ah[mt][2], ah[mt][3], bl[nt][0], bl[nt][1]);
                    mma_bf(Cf[mt][nt], al[mt][0], al[mt][1], al[mt][2], al[mt][3], bh[nt][0], bh[nt][1]);
                }
        }
    }

    // epilogue
#pragma unroll
    for (int mt = 0; mt < 2; mt++) {
        int row0 = m0 + wm * 32 + mt * 16 + g;
#pragma unroll
        for (int nt = 0; nt < 4; nt++) {
            int col = n0 + wn * 32 + nt * 8 + 2 * j;
            float b0 = bias[col], b1 = bias[col + 1];
            float2 v0 = make_float2(Cf[mt][nt][0] + b0, Cf[mt][nt][1] + b1);
            float2 v1 = make_float2(Cf[mt][nt][2] + b0, Cf[mt][nt][3] + b1);
            if (MODE == 1) {
                *(float2*)(Cout + (size_t)row0 * DIMC + col) = v0;
                *(float2*)(Cout + (size_t)(row0 + 8) * DIMC + col) = v1;
            } else {
                int s = (col >= 2 * DIMC) ? 2 : (col >= DIMC ? 1 : 0);
                int rr = col - s * DIMC;
                int hh = rr / HD;
                int d = rr - hh * HD;
                float* base = (s == 0) ? g_q : (s == 1) ? g_k : g_v;
                int bb0 = row0 >> 11, t0 = row0 & (SEQ - 1);
                int r1 = row0 + 8;
                int bb1 = r1 >> 11, t1 = r1 & (SEQ - 1);
                *(float2*)(base + ((size_t)(bb0 * NH + hh) * SEQ + t0) * HD + d) = v0;
                *(float2*)(base + ((size_t)(bb1 * NH + hh) * SEQ + t1) * HD + d) = v1;
            }
        }
    }
}

// ---------------------------------------------------------------------------
// RoPE in place on g_q, g_k.
// ---------------------------------------------------------------------------
__global__ __launch_bounds__(256)
void rope_kernel()
{
    int idx = blockIdx.x * blockDim.x + threadIdx.x;
    int j = idx % 48;
    int rest = idx / 48;
    int t = rest & (SEQ - 1);
    int bh = rest >> 11;

    float freq = exp2f(-(2.f * j / 96.f) * 13.287712379549449f);
    float ang = (float)t * freq;
    float sn, cs;
    sincosf(ang, &sn, &cs);

    size_t base = ((size_t)bh * SEQ + t) * HD;
    float q1 = g_q[base + j], q2 = g_q[base + j + 48];
    g_q[base + j]      = q1 * cs - q2 * sn;
    g_q[base + j + 48] = q2 * cs + q1 * sn;
    float k1 = g_k[base + j], k2 = g_k[base + j + 48];
    g_k[base + j]      = k1 * cs - k2 * sn;
    g_k[base + j + 48] = k2 * cs + k1 * sn;
}

// ---------------------------------------------------------------------------
// Flash attention via mma.sync tf32, 3-stage cp.async K/V ring.
// Writeback packs O into g_atth/g_attl (bf16 hi/lo) for the proj GEMM.
// ---------------------------------------------------------------------------
#define QLD 100
#define KLD 100
#define VLD 104
#define KVSTG (64*(KLD+VLD))
#define ATTN_SMEM ((128*QLD + 3*KVSTG) * 4)   // 207872

__global__ __launch_bounds__(256, 1)
void attn_mma()
{
    extern __shared__ float smf[];
    float* Qs = smf;
    float* KV = smf + 128 * QLD;

    int qt = gridDim.x - 1 - blockIdx.x;
    int hh = blockIdx.y, b = blockIdx.z;
    int tid = threadIdx.x;
    int lane = tid & 31;
    int wid = tid >> 5;
    int g = lane >> 2, j = lane & 3;
    const float scale = rsqrtf((float)HD);

    const float* Qg = g_q + ((size_t)(b * NH + hh) * SEQ + (size_t)qt * 128) * HD;
    const float* Kg = g_k + ((size_t)(b * NH + hh) * SEQ) * HD;
    const float* Vg = g_v + ((size_t)(b * NH + hh) * SEQ) * HD;

    int nkt = 2 * qt + 2;

    auto issue_kv = [&](int kt) {
        int st = kt % 3;
        float* Ks = KV + st * KVSTG;
        float* Vs = Ks + 64 * KLD;
        const float* kp = Kg + (size_t)kt * 64 * HD;
        const float* vp = Vg + (size_t)kt * 64 * HD;
#pragma unroll
        for (int it = 0; it < 6; it++) {
            int f = tid + it * 256;
            int r = f / 24, c4 = (f % 24) * 4;
            cp16(smem_u32(Ks + r * KLD + c4), kp + (size_t)r * HD + c4);
            cp16(smem_u32(Vs + r * VLD + c4), vp + (size_t)r * HD + c4);
        }
    };

    issue_kv(0); cp_commit();
    issue_kv(1); cp_commit();

    for (int f = tid; f < 128 * 24; f += 256) {
        int r = f / 24, c4 = (f % 24) * 4;
        float4 v = *(const float4*)(Qg + (size_t)r * HD + c4);
        v.x = __uint_as_float(f2tf(v.x * scale));
        v.y = __uint_as_float(f2tf(v.y * scale));
        v.z = __uint_as_float(f2tf(v.z * scale));
        v.w = __uint_as_float(f2tf(v.w * scale));
        *(float4*)(Qs + r * QLD + c4) = v;
    }

    float m0r = -1e30f, m1r = -1e30f, l0r = 0.f, l1r = 0.f;
    float O[12][4];
#pragma unroll
    for (int nt = 0; nt < 12; nt++)
#pragma unroll
        for (int r = 0; r < 4; r++) O[nt][r] = 0.f;

    int row0 = qt * 128 + wid * 16 + g;

    for (int kt = 0; kt < nkt; kt++) {
        cp_wait1();
        __syncthreads();
        if (kt + 2 < nkt) issue_kv(kt + 2);
        cp_commit();

        int st = kt % 3;
        const float* Ks = KV + st * KVSTG;
        const float* Vs = Ks + 64 * KLD;

        float S[8][4];
#pragma unroll
        for (int nt = 0; nt < 8; nt++)
#pragma unroll
            for (int r = 0; r < 4; r++) S[nt][r] = 0.f;

#pragma unroll
        for (int ks = 0; ks < 12; ks++) {
            int k0 = ks * 8;
            int qr = wid * 16 + g;
            uint32_t a0 = __float_as_uint(Qs[qr * QLD + k0 + j]);
            uint32_t a1 = __float_as_uint(Qs[(qr + 8) * QLD + k0 + j]);
            uint32_t a2 = __float_as_uint(Qs[qr * QLD + k0 + j + 4]);
            uint32_t a3 = __float_as_uint(Qs[(qr + 8) * QLD + k0 + j + 4]);
#pragma unroll
            for (int nt = 0; nt < 8; nt++) {
                uint32_t b0 = __float_as_uint(Ks[(nt * 8 + g) * KLD + k0 + j]);
                uint32_t b1 = __float_as_uint(Ks[(nt * 8 + g) * KLD + k0 + j + 4]);
                mma_tf(S[nt], a0, a1, a2, a3, b0, b1);
            }
        }

        if (kt >= nkt - 2) {
            int colb = kt * 64;
#pragma unroll
            for (int nt = 0; nt < 8; nt++) {
                int c0 = colb + nt * 8 + 2 * j;
                if (c0 > row0)     S[nt][0] = -1e30f;
                if (c0 + 1 > row0) S[nt][1] = -1e30f;
                if (c0 > row0 + 8)     S[nt][2] = -1e30f;
                if (c0 + 1 > row0 + 8) S[nt][3] = -1e30f;
            }
        }

        float mx0 = -1e30f, mx1 = -1e30f;
#pragma unroll
        for (int nt = 0; nt < 8; nt++) {
            mx0 = fmaxf(mx0, fmaxf(S[nt][0], S[nt][1]));
            mx1 = fmaxf(mx1, fmaxf(S[nt][2], S[nt][3]));
        }
        mx0 = fmaxf(mx0, __shfl_xor_sync(0xffffffffu, mx0, 1));
        mx0 = fmaxf(mx0, __shfl_xor_sync(0xffffffffu, mx0, 2));
        mx1 = fmaxf(mx1, __shfl_xor_sync(0xffffffffu, mx1, 1));
        mx1 = fmaxf(mx1, __shfl_xor_sync(0xffffffffu, mx1, 2));

        float mn0 = fmaxf(m0r, mx0), mn1 = fmaxf(m1r, mx1);
        float al0 = __expf(m0r - mn0), al1 = __expf(m1r - mn1);
        float s0 = 0.f, s1 = 0.f;
#pragma unroll
        for (int nt = 0; nt < 8; nt++) {
            S[nt][0] = __expf(S[nt][0] - mn0);
            S[nt][1] = __expf(S[nt][1] - mn0);
            S[nt][2] = __expf(S[nt][2] - mn1);
            S[nt][3] = __expf(S[nt][3] - mn1);
            s0 += S[nt][0] + S[nt][1];
            s1 += S[nt][2] + S[nt][3];
        }
        s0 += __shfl_xor_sync(0xffffffffu, s0, 1);
        s0 += __shfl_xor_sync(0xffffffffu, s0, 2);
        s1 += __shfl_xor_sync(0xffffffffu, s1, 1);
        s1 += __shfl_xor_sync(0xffffffffu, s1, 2);
        l0r = l0r * al0 + s0;
        l1r = l1r * al1 + s1;
        m0r = mn0; m1r = mn1;
#pragma unroll
        for (int nt = 0; nt < 12; nt++) {
            O[nt][0] *= al0; O[nt][1] *= al0;
            O[nt][2] *= al1; O[nt][3] *= al1;
        }

        int src_lo = (lane & ~3) | (j >> 1);
        int par = j & 1;
#pragma unroll
        for (int ks = 0; ks < 8; ks++) {
            float p00 = __shfl_sync(0xffffffffu, S[ks][0], src_lo);
            float p01 = __shfl_sync(0xffffffffu, S[ks][1], src_lo);
            float p10 = __shfl_sync(0xffffffffu, S[ks][0], src_lo + 2);
            float p11 = __shfl_sync(0xffffffffu, S[ks][1], src_lo + 2);
            float p20 = __shfl_sync(0xffffffffu, S[ks][2], src_lo);
            float p21 = __shfl_sync(0xffffffffu, S[ks][3], src_lo);
            float p30 = __shfl_sync(0xffffffffu, S[ks][2], src_lo + 2);
            float p31 = __shfl_sync(0xffffffffu, S[ks][3], src_lo + 2);
            uint32_t a0 = f2tf(par ? p01 : p00);
            uint32_t a1 = f2tf(par ? p21 : p20);
            uint32_t a2 = f2tf(par ? p11 : p10);
            uint32_t a3 = f2tf(par ? p31 : p30);
#pragma unroll
            for (int nt = 0; nt < 12; nt++) {
                uint32_t b0 = __float_as_uint(Vs[(ks * 8 + j) * VLD + nt * 8 + g]);
                uint32_t b1 = __float_as_uint(Vs[(ks * 8 + j + 4) * VLD + nt * 8 + g]);
                mma_tf(O[nt], a0, a1, a2, a3, b0, b1);
            }
        }
        __syncthreads();
    }

    // writeback: pack O into bf16 hi/lo word arrays for the proj GEMM
    float inv0 = 1.f / l0r, inv1 = 1.f / l1r;
    size_t wbase0 = (((size_t)b * SEQ + row0) * DIMC + hh * HD) >> 1;
    size_t wbase1 = (((size_t)b * SEQ + row0 + 8) * DIMC + hh * HD) >> 1;
#pragma unroll
    for (int nt = 0; nt < 12; nt++) {
        int dw = (nt * 8 + 2 * j) >> 1;
        uint32_t h0, l0, h1, l1;
        split_bf2(O[nt][0] * inv0, O[nt][1] * inv0, h0, l0);
        split_bf2(O[nt][2] * inv1, O[nt][3] * inv1, h1, l1);
        g_atth[wbase0 + dw] = h0; g_attl[wbase0 + dw] = l0;
        g_atth[wbase1 + dw] = h1; g_attl[wbase1 + dw] = l1;
    }
}

// ---------------------------------------------------------------------------
// Launch
// Inputs: 0=x, 1=mask (ignored, causal), 2=w_qkv, 3=b_qkv, 4=w_proj, 5=b_proj
// ---------------------------------------------------------------------------
extern "C" void kernel_launch(void* const* d_in, const int* in_sizes, int n_in,
                              void* d_out, int out_size)
{
    const float* x      = (const float*)d_in[0];
    const float* w_qkv  = (const float*)d_in[2];
    const float* b_qkv  = (const float*)d_in[3];
    const float* w_proj = (const float*)d_in[4];
    const float* b_proj = (const float*)d_in[5];
    float* out = (float*)d_out;

    cudaFuncSetAttribute(attn_mma, cudaFuncAttributeMaxDynamicSharedMemorySize,
                         ATTN_SMEM);
    cudaFuncSetAttribute(gemm_mma<0>, cudaFuncAttributeMaxDynamicSharedMemorySize,
                         GEMM_SMEM_BYTES);
    cudaFuncSetAttribute(gemm_mma<1>, cudaFuncAttributeMaxDynamicSharedMemorySize,
                         GEMM_SMEM_BYTES);

    uint32_t *xh, *xl, *wqh, *wql, *wph, *wpl, *ath, *atl;
    cudaGetSymbolAddress((void**)&xh,  g_xh);
    cudaGetSymbolAddress((void**)&xl,  g_xl);
    cudaGetSymbolAddress((void**)&wqh, g_wqh);
    cudaGetSymbolAddress((void**)&wql, g_wql);
    cudaGetSymbolAddress((void**)&wph, g_wph);
    cudaGetSymbolAddress((void**)&wpl, g_wpl);
    cudaGetSymbolAddress((void**)&ath, g_atth);
    cudaGetSymbolAddress((void**)&atl, g_attl);

    // pack operands to bf16 hi/lo
    pack_kernel<<<(MTOT * KW + 255) / 256, 256>>>(x, xh, xl, MTOT * KW);
    pack_kernel<<<(3 * DIMC * KW + 255) / 256, 256>>>(w_qkv, wqh, wql, 3 * DIMC * KW);
    pack_kernel<<<(DIMC * KW + 255) / 256, 256>>>(w_proj, wph, wpl, DIMC * KW);

    // QKV: M=8192, N=2304
    gemm_mma<0><<<dim3(2304 / 128, MTOT / 128), 512, GEMM_SMEM_BYTES>>>(
        xh, xl, wqh, wql, b_qkv, nullptr);

    // RoPE
    rope_kernel<<<(BATCH * NH * SEQ * 48) / 256, 256>>>();

    // Attention
    attn_mma<<<dim3(SEQ / 128, NH, BATCH), 256, ATTN_SMEM>>>();

    // Projection: M=8192, N=768
    gemm_mma<1><<<dim3(DIMC / 128, MTOT / 128), 512, GEMM_SMEM_BYTES>>>(
        ath, atl, wph, wpl, b_proj, out);
}

// round 7
// speedup vs baseline: 3.5248x; 1.1880x over previous
#include <cuda_runtime.h>
#include <math.h>
#include <stdint.h>

#define DIMC 768
#define NH 8
#define HD 96
#define BATCH 4
#define SEQ 2048
#define MTOT (BATCH*SEQ)

// Scratch (static device arrays; no cudaMalloc allowed)
__device__ float g_q[(size_t)BATCH*NH*SEQ*HD];
__device__ float g_k[(size_t)BATCH*NH*SEQ*HD];
__device__ float g_vt[(size_t)BATCH*NH*HD*SEQ];    // V transposed: [b,h,d,t]
__device__ float g_att[(size_t)MTOT*DIMC];
__device__ float g_xr[(size_t)MTOT*DIMC];          // tf32-rounded x
__device__ float g_wqr[(size_t)3*DIMC*DIMC];       // tf32-rounded w_qkv
__device__ float g_wpr[(size_t)DIMC*DIMC];         // tf32-rounded w_proj

// ---------------------------------------------------------------------------
// helpers
// ---------------------------------------------------------------------------
__device__ __forceinline__ uint32_t smem_u32(const void* p) {
    uint32_t a;
    asm("{ .reg .u64 t; cvta.to.shared.u64 t, %1; cvt.u32.u64 %0, t; }" : "=r"(a) : "l"(p));
    return a;
}
__device__ __forceinline__ void cp16(uint32_t s, const void* g) {
    asm volatile("cp.async.ca.shared.global [%0], [%1], 16;" :: "r"(s), "l"(g) : "memory");
}
__device__ __forceinline__ void cp_commit() {
    asm volatile("cp.async.commit_group;" ::: "memory");
}
__device__ __forceinline__ void cp_wait1() {
    asm volatile("cp.async.wait_group 1;" ::: "memory");
}
__device__ __forceinline__ uint32_t f2tf(float x) {
    uint32_t r;
    asm("cvt.rna.tf32.f32 %0, %1;" : "=r"(r) : "f"(x));
    return r;
}
__device__ __forceinline__ void ldsm4(uint32_t& r0, uint32_t& r1, uint32_t& r2,
                                      uint32_t& r3, uint32_t addr) {
    asm volatile("ldmatrix.sync.aligned.m8n8.x4.shared.b16 {%0,%1,%2,%3}, [%4];"
                 : "=r"(r0), "=r"(r1), "=r"(r2), "=r"(r3) : "r"(addr));
}
__device__ __forceinline__ void mma_tf(float d[4], uint32_t a0, uint32_t a1,
                                       uint32_t a2, uint32_t a3,
                                       uint32_t b0, uint32_t b1) {
    asm volatile(
        "mma.sync.aligned.m16n8k8.row.col.f32.tf32.tf32.f32 "
        "{%0,%1,%2,%3},{%4,%5,%6,%7},{%8,%9},{%0,%1,%2,%3};"
        : "+f"(d[0]), "+f"(d[1]), "+f"(d[2]), "+f"(d[3])
        : "r"(a0), "r"(a1), "r"(a2), "r"(a3), "r"(b0), "r"(b1));
}

// ---------------------------------------------------------------------------
// round-to-tf32 copy
// ---------------------------------------------------------------------------
__global__ __launch_bounds__(256)
void round_tf_kernel(const float* __restrict__ src, float* __restrict__ dst, int n4)
{
    int i = blockIdx.x * blockDim.x + threadIdx.x;
    if (i < n4) {
        float4 v = ((const float4*)src)[i];
        v.x = __uint_as_float(f2tf(v.x));
        v.y = __uint_as_float(f2tf(v.y));
        v.z = __uint_as_float(f2tf(v.z));
        v.w = __uint_as_float(f2tf(v.w));
        ((float4*)dst)[i] = v;
    }
}

// ---------------------------------------------------------------------------
// GEMM v4: single-pass tf32, raw f32 tiles, ldmatrix frags, 3-stage cp.async.
// C[M,N] = A[M,768] @ W[N,768]^T + bias ; 512 threads, 4x4 warps, tile 128x128.
// MODE 0: scatter into g_q/g_k/g_vt(transposed). MODE 1: write Cout.
// ---------------------------------------------------------------------------
#define GSTRIDE 36                  // f32 row stride (32 + 4 pad; 144B, ldsm-safe)
#define GTSZ (128*GSTRIDE)          // words per array-stage
#define GEMM_SMEM_BYTES (3*2*GTSZ*4)   // 110592

template<int MODE>
__global__ __launch_bounds__(512, 1)
void gemm_tf32(const float* __restrict__ A, const float* __restrict__ W,
               const float* __restrict__ bias, float* __restrict__ Cout)
{
    extern __shared__ float smf[];

    int tid = threadIdx.x;
    int lane = tid & 31;
    int wid = tid >> 5;
    int g = lane >> 2, j = lane & 3;
    int wm = wid & 3, wn = wid >> 2;
    int m0 = blockIdx.y * 128;
    int n0 = blockIdx.x * 128;

    // loader: 512 threads cover 128 rows x 32 f32 per array (2 cp16 each)
    int lrow = tid >> 2;
    int lc = (tid & 3) * 8;
    const float* srcA = A + (size_t)(m0 + lrow) * DIMC + lc;
    const float* srcW = W + (size_t)(n0 + lrow) * DIMC + lc;
    uint32_t dstoff = smem_u32(smf) + (uint32_t)(lrow * GSTRIDE + lc) * 4;

    auto issue = [&](int c) {
        uint32_t ab = dstoff + (uint32_t)((c % 3) * 2 * GTSZ) * 4;
        cp16(ab,      srcA + c * 32);
        cp16(ab + 16, srcA + c * 32 + 4);
        uint32_t wb = ab + (uint32_t)GTSZ * 4;
        cp16(wb,      srcW + c * 32);
        cp16(wb + 16, srcW + c * 32 + 4);
    };

    uint32_t smb = smem_u32(smf);
    int aRow = wm * 32 + ((lane >> 3) & 1) * 8 + (lane & 7);   // + mt*16
    int aColW = (lane >> 4) * 4;                               // + ks*8
    int bRow = wn * 32 + ((lane >> 4) & 1) * 8 + (lane & 7);   // + bk*16
    int bColW = ((lane >> 3) & 1) * 4;                         // + ks*8

    float Cf[2][4][4];
#pragma unroll
    for (int mt = 0; mt < 2; mt++)
#pragma unroll
        for (int nt = 0; nt < 4; nt++)
#pragma unroll
            for (int r = 0; r < 4; r++) Cf[mt][nt][r] = 0.f;

    issue(0); cp_commit();
    issue(1); cp_commit();

    const int NC = DIMC / 32;   // 24
    for (int c = 0; c < NC; c++) {
        cp_wait1();
        __syncthreads();
        if (c + 2 < NC) issue(c + 2);
        cp_commit();

        uint32_t stA = smb + (uint32_t)((c % 3) * 2 * GTSZ) * 4;
        uint32_t stW = stA + (uint32_t)GTSZ * 4;

#pragma unroll
        for (int ks = 0; ks < 4; ks++) {
            uint32_t a[2][4], b[4][2];
#pragma unroll
            for (int mt = 0; mt < 2; mt++)
                ldsm4(a[mt][0], a[mt][1], a[mt][2], a[mt][3],
                      stA + (uint32_t)((aRow + mt * 16) * GSTRIDE + ks * 8 + aColW) * 4);
#pragma unroll
            for (int bk = 0; bk < 2; bk++)
                ldsm4(b[2*bk][0], b[2*bk][1], b[2*bk+1][0], b[2*bk+1][1],
                      stW + (uint32_t)((bRow + bk * 16) * GSTRIDE + ks * 8 + bColW) * 4);
#pragma unroll
            for (int mt = 0; mt < 2; mt++)
#pragma unroll
                for (int nt = 0; nt < 4; nt++)
                    mma_tf(Cf[mt][nt], a[mt][0], a[mt][1], a[mt][2], a[mt][3],
                           b[nt][0], b[nt][1]);
        }
    }

    // epilogue
#pragma unroll
    for (int mt = 0; mt < 2; mt++) {
        int row0 = m0 + wm * 32 + mt * 16 + g;
#pragma unroll
        for (int nt = 0; nt < 4; nt++) {
            int col = n0 + wn * 32 + nt * 8 + 2 * j;
            float b0 = bias[col], b1 = bias[col + 1];
            float2 v0 = make_float2(Cf[mt][nt][0] + b0, Cf[mt][nt][1] + b1);
            float2 v1 = make_float2(Cf[mt][nt][2] + b0, Cf[mt][nt][3] + b1);
            if (MODE == 1) {
                *(float2*)(Cout + (size_t)row0 * DIMC + col) = v0;
                *(float2*)(Cout + (size_t)(row0 + 8) * DIMC + col) = v1;
            } else {
                int s = (col >= 2 * DIMC) ? 2 : (col >= DIMC ? 1 : 0);
                int rr = col - s * DIMC;
                int hh = rr / HD;
                int d = rr - hh * HD;
                int bb0 = row0 >> 11, t0 = row0 & (SEQ - 1);
                int r1 = row0 + 8;
                int bb1 = r1 >> 11, t1 = r1 & (SEQ - 1);
                if (s == 2) {
                    float* dv0 = g_vt + ((size_t)(bb0 * NH + hh) * HD + d) * SEQ + t0;
                    dv0[0] = v0.x; dv0[SEQ] = v0.y;
                    float* dv1 = g_vt + ((size_t)(bb1 * NH + hh) * HD + d) * SEQ + t1;
                    dv1[0] = v1.x; dv1[SEQ] = v1.y;
                } else {
                    float* base = (s == 0) ? g_q : g_k;
                    *(float2*)(base + ((size_t)(bb0 * NH + hh) * SEQ + t0) * HD + d) = v0;
                    *(float2*)(base + ((size_t)(bb1 * NH + hh) * SEQ + t1) * HD + d) = v1;
                }
            }
        }
    }
}

// ---------------------------------------------------------------------------
// RoPE in place on g_q, g_k.
// ---------------------------------------------------------------------------
__global__ __launch_bounds__(256)
void rope_kernel()
{
    int idx = blockIdx.x * blockDim.x + threadIdx.x;
    int j = idx % 48;
    int rest = idx / 48;
    int t = rest & (SEQ - 1);
    int bh = rest >> 11;

    float freq = exp2f(-(2.f * j / 96.f) * 13.287712379549449f);
    float ang = (float)t * freq;
    float sn, cs;
    sincosf(ang, &sn, &cs);

    size_t base = ((size_t)bh * SEQ + t) * HD;
    float q1 = g_q[base + j], q2 = g_q[base + j + 48];
    g_q[base + j]      = q1 * cs - q2 * sn;
    g_q[base + j + 48] = q2 * cs + q1 * sn;
    float k1 = g_k[base + j], k2 = g_k[base + j + 48];
    g_k[base + j]      = k1 * cs - k2 * sn;
    g_k[base + j + 48] = k2 * cs + k1 * sn;
}

// ---------------------------------------------------------------------------
// Flash attention v3: tf32 mma, ldmatrix fragments, V pre-transposed (g_vt),
// 3-stage cp.async K/Vt ring. Block = (qtile 128, h, b), 256 threads.
// ---------------------------------------------------------------------------
#define QLD 100
#define KLD 100
#define VTLD 68
#define KVSTG (64*KLD + 96*VTLD)
#define ATTN_SMEM ((128*QLD + 3*KVSTG) * 4)   // 206336

__global__ __launch_bounds__(256, 1)
void attn_mma()
{
    extern __shared__ float smf[];
    float* Qs = smf;                 // [128][QLD]
    float* KV = smf + 128 * QLD;     // 3 stages of K[64][KLD] + Vt[96][VTLD]

    int qt = gridDim.x - 1 - blockIdx.x;
    int hh = blockIdx.y, b = blockIdx.z;
    int tid = threadIdx.x;
    int lane = tid & 31;
    int wid = tid >> 5;
    int g = lane >> 2, j = lane & 3;
    const float scale = rsqrtf((float)HD);

    const float* Qg = g_q + ((size_t)(b * NH + hh) * SEQ + (size_t)qt * 128) * HD;
    const float* Kg = g_k + ((size_t)(b * NH + hh) * SEQ) * HD;
    const float* Vtg = g_vt + ((size_t)(b * NH + hh) * HD) * SEQ;

    int nkt = 2 * qt + 2;

    auto issue_kv = [&](int kt) {
        int st = kt % 3;
        float* Ks = KV + st * KVSTG;
        float* Vs = Ks + 64 * KLD;
        const float* kp = Kg + (size_t)kt * 64 * HD;
#pragma unroll
        for (int it = 0; it < 6; it++) {
            int f = tid + it * 256;
            int r = f / 24, c4 = (f % 24) * 4;
            cp16(smem_u32(Ks + r * KLD + c4), kp + (size_t)r * HD + c4);
        }
        const float* vp = Vtg + kt * 64;
#pragma unroll
        for (int it = 0; it < 6; it++) {
            int f = tid + it * 256;
            int d = f >> 4, c4 = (f & 15) * 4;
            cp16(smem_u32(Vs + d * VTLD + c4), vp + (size_t)d * SEQ + c4);
        }
    };

    issue_kv(0); cp_commit();
    issue_kv(1); cp_commit();

    for (int f = tid; f < 128 * 24; f += 256) {
        int r = f / 24, c4 = (f % 24) * 4;
        float4 v = *(const float4*)(Qg + (size_t)r * HD + c4);
        v.x = __uint_as_float(f2tf(v.x * scale));
        v.y = __uint_as_float(f2tf(v.y * scale));
        v.z = __uint_as_float(f2tf(v.z * scale));
        v.w = __uint_as_float(f2tf(v.w * scale));
        *(float4*)(Qs + r * QLD + c4) = v;
    }

    // fragment address bases
    uint32_t qsb = smem_u32(Qs);
    int qRow = wid * 16 + ((lane >> 3) & 1) * 8 + (lane & 7);
    int qColW = (lane >> 4) * 4;
    int bRow = ((lane >> 4) & 1) * 8 + (lane & 7);    // + bk*16
    int bColW = ((lane >> 3) & 1) * 4;                // + ks*8

    float m0r = -1e30f, m1r = -1e30f, l0r = 0.f, l1r = 0.f;
    float O[12][4];
#pragma unroll
    for (int nt = 0; nt < 12; nt++)
#pragma unroll
        for (int r = 0; r < 4; r++) O[nt][r] = 0.f;

    int row0 = qt * 128 + wid * 16 + g;

    for (int kt = 0; kt < nkt; kt++) {
        cp_wait1();
        __syncthreads();
        if (kt + 2 < nkt) issue_kv(kt + 2);
        cp_commit();

        int st = kt % 3;
        uint32_t ksb = smem_u32(KV + st * KVSTG);
        uint32_t vsb = ksb + (uint32_t)(64 * KLD) * 4;

        // ---- S = Q @ K^T ----
        float S[8][4];
#pragma unroll
        for (int nt = 0; nt < 8; nt++)
#pragma unroll
            for (int r = 0; r < 4; r++) S[nt][r] = 0.f;

#pragma unroll
        for (int ks = 0; ks < 12; ks++) {
            uint32_t a0, a1, a2, a3;
            ldsm4(a0, a1, a2, a3, qsb + (uint32_t)(qRow * QLD + ks * 8 + qColW) * 4);
            uint32_t bfr[8][2];
#pragma unroll
            for (int bk = 0; bk < 4; bk++)
                ldsm4(bfr[2*bk][0], bfr[2*bk][1], bfr[2*bk+1][0], bfr[2*bk+1][1],
                      ksb + (uint32_t)((bRow + bk * 16) * KLD + ks * 8 + bColW) * 4);
#pragma unroll
            for (int nt = 0; nt < 8; nt++)
                mma_tf(S[nt], a0, a1, a2, a3, bfr[nt][0], bfr[nt][1]);
        }

        if (kt >= nkt - 2) {
            int colb = kt * 64;
#pragma unroll
            for (int nt = 0; nt < 8; nt++) {
                int c0 = colb + nt * 8 + 2 * j;
                if (c0 > row0)     S[nt][0] = -1e30f;
                if (c0 + 1 > row0) S[nt][1] = -1e30f;
                if (c0 > row0 + 8)     S[nt][2] = -1e30f;
                if (c0 + 1 > row0 + 8) S[nt][3] = -1e30f;
            }
        }

        // ---- online softmax ----
        float mx0 = -1e30f, mx1 = -1e30f;
#pragma unroll
        for (int nt = 0; nt < 8; nt++) {
            mx0 = fmaxf(mx0, fmaxf(S[nt][0], S[nt][1]));
            mx1 = fmaxf(mx1, fmaxf(S[nt][2], S[nt][3]));
        }
        mx0 = fmaxf(mx0, __shfl_xor_sync(0xffffffffu, mx0, 1));
        mx0 = fmaxf(mx0, __shfl_xor_sync(0xffffffffu, mx0, 2));
        mx1 = fmaxf(mx1, __shfl_xor_sync(0xffffffffu, mx1, 1));
        mx1 = fmaxf(mx1, __shfl_xor_sync(0xffffffffu, mx1, 2));

        float mn0 = fmaxf(m0r, mx0), mn1 = fmaxf(m1r, mx1);
        float al0 = __expf(m0r - mn0), al1 = __expf(m1r - mn1);
        float s0 = 0.f, s1 = 0.f;
#pragma unroll
        for (int nt = 0; nt < 8; nt++) {
            S[nt][0] = __expf(S[nt][0] - mn0);
            S[nt][1] = __expf(S[nt][1] - mn0);
            S[nt][2] = __expf(S[nt][2] - mn1);
            S[nt][3] = __expf(S[nt][3] - mn1);
            s0 += S[nt][0] + S[nt][1];
            s1 += S[nt][2] + S[nt][3];
        }
        s0 += __shfl_xor_sync(0xffffffffu, s0, 1);
        s0 += __shfl_xor_sync(0xffffffffu, s0, 2);
        s1 += __shfl_xor_sync(0xffffffffu, s1, 1);
        s1 += __shfl_xor_sync(0xffffffffu, s1, 2);
        l0r = l0r * al0 + s0;
        l1r = l1r * al1 + s1;
        m0r = mn0; m1r = mn1;
#pragma unroll
        for (int nt = 0; nt < 12; nt++) {
            O[nt][0] *= al0; O[nt][1] *= al0;
            O[nt][2] *= al1; O[nt][3] *= al1;
        }

        // ---- O += P @ V (V fragments from transposed tile) ----
        int src_lo = (lane & ~3) | (j >> 1);
        int par = j & 1;
#pragma unroll
        for (int ks = 0; ks < 8; ks++) {
            float p00 = __shfl_sync(0xffffffffu, S[ks][0], src_lo);
            float p01 = __shfl_sync(0xffffffffu, S[ks][1], src_lo);
            float p10 = __shfl_sync(0xffffffffu, S[ks][0], src_lo + 2);
            float p11 = __shfl_sync(0xffffffffu, S[ks][1], src_lo + 2);
            float p20 = __shfl_sync(0xffffffffu, S[ks][2], src_lo);
            float p21 = __shfl_sync(0xffffffffu, S[ks][3], src_lo);
            float p30 = __shfl_sync(0xffffffffu, S[ks][2], src_lo + 2);
            float p31 = __shfl_sync(0xffffffffu, S[ks][3], src_lo + 2);
            uint32_t a0 = f2tf(par ? p01 : p00);
            uint32_t a1 = f2tf(par ? p21 : p20);
            uint32_t a2 = f2tf(par ? p11 : p10);
            uint32_t a3 = f2tf(par ? p31 : p30);
            uint32_t bfr[12][2];
#pragma unroll
            for (int bk = 0; bk < 6; bk++)
                ldsm4(bfr[2*bk][0], bfr[2*bk][1], bfr[2*bk+1][0], bfr[2*bk+1][1],
                      vsb + (uint32_t)((bRow + bk * 16) * VTLD + ks * 8 + bColW) * 4);
#pragma unroll
            for (int nt = 0; nt < 12; nt++)
                mma_tf(O[nt], a0, a1, a2, a3, bfr[nt][0], bfr[nt][1]);
        }
        __syncthreads();
    }

    // writeback O / l -> g_att (tf32-rounded for the proj GEMM)
    float inv0 = 1.f / l0r, inv1 = 1.f / l1r;
    float* outb = g_att + ((size_t)b * SEQ + row0) * DIMC + hh * HD;
#pragma unroll
    for (int nt = 0; nt < 12; nt++) {
        int d = nt * 8 + 2 * j;
        float2 v0 = make_float2(__uint_as_float(f2tf(O[nt][0] * inv0)),
                                __uint_as_float(f2tf(O[nt][1] * inv0)));
        float2 v1 = make_float2(__uint_as_float(f2tf(O[nt][2] * inv1)),
                                __uint_as_float(f2tf(O[nt][3] * inv1)));
        *(float2*)(outb + d) = v0;
        *(float2*)(outb + (size_t)8 * DIMC + d) = v1;
    }
}

// ---------------------------------------------------------------------------
// Launch
// Inputs: 0=x, 1=mask (ignored, causal), 2=w_qkv, 3=b_qkv, 4=w_proj, 5=b_proj
// ---------------------------------------------------------------------------
extern "C" void kernel_launch(void* const* d_in, const int* in_sizes, int n_in,
                              void* d_out, int out_size)
{
    const float* x      = (const float*)d_in[0];
    const float* w_qkv  = (const float*)d_in[2];
    const float* b_qkv  = (const float*)d_in[3];
    const float* w_proj = (const float*)d_in[4];
    const float* b_proj = (const float*)d_in[5];
    float* out = (float*)d_out;

    cudaFuncSetAttribute(attn_mma, cudaFuncAttributeMaxDynamicSharedMemorySize,
                         ATTN_SMEM);
    cudaFuncSetAttribute(gemm_tf32<0>, cudaFuncAttributeMaxDynamicSharedMemorySize,
                         GEMM_SMEM_BYTES);
    cudaFuncSetAttribute(gemm_tf32<1>, cudaFuncAttributeMaxDynamicSharedMemorySize,
                         GEMM_SMEM_BYTES);

    float *xr, *wqr, *wpr, *attp;
    cudaGetSymbolAddress((void**)&xr,  g_xr);
    cudaGetSymbolAddress((void**)&wqr, g_wqr);
    cudaGetSymbolAddress((void**)&wpr, g_wpr);
    cudaGetSymbolAddress((void**)&attp, g_att);

    // tf32-round operands (removes truncation bias in mma)
    round_tf_kernel<<<(MTOT * DIMC / 4 + 255) / 256, 256>>>(x, xr, MTOT * DIMC / 4);
    round_tf_kernel<<<(3 * DIMC * DIMC / 4 + 255) / 256, 256>>>(w_qkv, wqr, 3 * DIMC * DIMC / 4);
    round_tf_kernel<<<(DIMC * DIMC / 4 + 255) / 256, 256>>>(w_proj, wpr, DIMC * DIMC / 4);

    // QKV: M=8192, N=2304
    gemm_tf32<0><<<dim3(2304 / 128, MTOT / 128), 512, GEMM_SMEM_BYTES>>>(
        xr, wqr, b_qkv, nullptr);

    // RoPE
    rope_kernel<<<(BATCH * NH * SEQ * 48) / 256, 256>>>();

    // Attention
    attn_mma<<<dim3(SEQ / 128, NH, BATCH), 256, ATTN_SMEM>>>();

    // Projection: M=8192, N=768
    gemm_tf32<1><<<dim3(DIMC / 128, MTOT / 128), 512, GEMM_SMEM_BYTES>>>(
        attp, wpr, b_proj, out);
}

// round 8
// speedup vs baseline: 3.8033x; 1.0790x over previous
#include <cuda_runtime.h>
#include <math.h>
#include <stdint.h>

#define DIMC 768
#define NH 8
#define HD 96
#define BATCH 4
#define SEQ 2048
#define MTOT (BATCH*SEQ)

// Scratch (static device arrays; no cudaMalloc allowed)
__device__ float g_q[(size_t)BATCH*NH*SEQ*HD];
__device__ float g_k[(size_t)BATCH*NH*SEQ*HD];
__device__ float g_vt[(size_t)BATCH*NH*HD*SEQ];    // V transposed: [b,h,d,t]
__device__ float g_att[(size_t)MTOT*DIMC];
__device__ float g_xr[(size_t)MTOT*DIMC];          // tf32-rounded x
__device__ float g_wqr[(size_t)3*DIMC*DIMC];       // tf32-rounded w_qkv
__device__ float g_wpr[(size_t)DIMC*DIMC];         // tf32-rounded w_proj

// ---------------------------------------------------------------------------
// helpers
// ---------------------------------------------------------------------------
__device__ __forceinline__ uint32_t smem_u32(const void* p) {
    uint32_t a;
    asm("{ .reg .u64 t; cvta.to.shared.u64 t, %1; cvt.u32.u64 %0, t; }" : "=r"(a) : "l"(p));
    return a;
}
__device__ __forceinline__ void cp16(uint32_t s, const void* g) {
    asm volatile("cp.async.ca.shared.global [%0], [%1], 16;" :: "r"(s), "l"(g) : "memory");
}
__device__ __forceinline__ void cp_commit() {
    asm volatile("cp.async.commit_group;" ::: "memory");
}
__device__ __forceinline__ void cp_wait1() {
    asm volatile("cp.async.wait_group 1;" ::: "memory");
}
__device__ __forceinline__ uint32_t f2tf(float x) {
    uint32_t r;
    asm("cvt.rna.tf32.f32 %0, %1;" : "=r"(r) : "f"(x));
    return r;
}
__device__ __forceinline__ void ldsm4(uint32_t& r0, uint32_t& r1, uint32_t& r2,
                                      uint32_t& r3, uint32_t addr) {
    asm volatile("ldmatrix.sync.aligned.m8n8.x4.shared.b16 {%0,%1,%2,%3}, [%4];"
                 : "=r"(r0), "=r"(r1), "=r"(r2), "=r"(r3) : "r"(addr));
}
__device__ __forceinline__ void mma_tf(float d[4], uint32_t a0, uint32_t a1,
                                       uint32_t a2, uint32_t a3,
                                       uint32_t b0, uint32_t b1) {
    asm volatile(
        "mma.sync.aligned.m16n8k8.row.col.f32.tf32.tf32.f32 "
        "{%0,%1,%2,%3},{%4,%5,%6,%7},{%8,%9},{%0,%1,%2,%3};"
        : "+f"(d[0]), "+f"(d[1]), "+f"(d[2]), "+f"(d[3])
        : "r"(a0), "r"(a1), "r"(a2), "r"(a3), "r"(b0), "r"(b1));
}

// ---------------------------------------------------------------------------
// round-to-tf32 copy
// ---------------------------------------------------------------------------
__global__ __launch_bounds__(256)
void round_tf_kernel(const float* __restrict__ src, float* __restrict__ dst, int n4)
{
    int i = blockIdx.x * blockDim.x + threadIdx.x;
    if (i < n4) {
        float4 v = ((const float4*)src)[i];
        v.x = __uint_as_float(f2tf(v.x));
        v.y = __uint_as_float(f2tf(v.y));
        v.z = __uint_as_float(f2tf(v.z));
        v.w = __uint_as_float(f2tf(v.w));
        ((float4*)dst)[i] = v;
    }
}

// ---------------------------------------------------------------------------
// GEMM v5: tf32 mma, CTA tile 128(M) x 256(N), 8 warps (2x4), warp tile 64x64.
// 3-stage cp.async ring, ldmatrix fragments, 8 ldsm : 32 mma per k8 per warp.
// MODE 0: scatter into g_q/g_k/g_vt(transposed). MODE 1: write Cout.
// ---------------------------------------------------------------------------
#define GSTR 36                       // f32 row stride (32 + 4 pad)
#define ASZ (128*GSTR)
#define WSZ (256*GSTR)
#define STG (ASZ+WSZ)
#define GEMM_SMEM_BYTES (3*STG*4)     // 165888

template<int MODE>
__global__ __launch_bounds__(256, 1)
void gemm_tf32(const float* __restrict__ A, const float* __restrict__ W,
               const float* __restrict__ bias, float* __restrict__ Cout)
{
    extern __shared__ float smf[];
    uint32_t smb = smem_u32(smf);

    int tid = threadIdx.x;
    int lane = tid & 31;
    int wid = tid >> 5;              // 0..7
    int g = lane >> 2, j = lane & 3;
    int wm = wid & 1, wn = wid >> 1; // 2 x 4 warp grid, warp tile 64x64
    int m0 = blockIdx.y * 128;
    int n0 = blockIdx.x * 256;

    auto issue = [&](int c) {
        uint32_t stb = smb + (uint32_t)((c % 3) * STG) * 4;
#pragma unroll
        for (int it = 0; it < 12; it++) {
            int f = tid + it * 256;
            int row = f >> 3;
            int c4 = (f & 7) * 4;
            if (it < 4) {
                cp16(stb + (uint32_t)(row * GSTR + c4) * 4,
                     A + (size_t)(m0 + row) * DIMC + c * 32 + c4);
            } else {
                int wrow = row - 128;
                cp16(stb + (uint32_t)(ASZ + wrow * GSTR + c4) * 4,
                     W + (size_t)(n0 + wrow) * DIMC + c * 32 + c4);
            }
        }
    };

    // fragment address bases
    int aRowB = wm * 64 + ((lane >> 3) & 1) * 8 + (lane & 7);   // + mt*16
    int aColW = (lane >> 4) * 4;                                // + ks*8
    int bRowB = wn * 64 + ((lane >> 4) & 1) * 8 + (lane & 7);   // + bk*16
    int bColW = ((lane >> 3) & 1) * 4;                          // + ks*8

    float Cf[4][8][4];
#pragma unroll
    for (int mt = 0; mt < 4; mt++)
#pragma unroll
        for (int nt = 0; nt < 8; nt++)
#pragma unroll
            for (int r = 0; r < 4; r++) Cf[mt][nt][r] = 0.f;

    issue(0); cp_commit();
    issue(1); cp_commit();

    const int NC = DIMC / 32;   // 24
    for (int c = 0; c < NC; c++) {
        cp_wait1();
        __syncthreads();
        if (c + 2 < NC) issue(c + 2);
        cp_commit();

        uint32_t stA = smb + (uint32_t)((c % 3) * STG) * 4;
        uint32_t stW = stA + (uint32_t)ASZ * 4;

#pragma unroll
        for (int ks = 0; ks < 4; ks++) {
            uint32_t a[4][4], b[8][2];
#pragma unroll
            for (int mt = 0; mt < 4; mt++)
                ldsm4(a[mt][0], a[mt][1], a[mt][2], a[mt][3],
                      stA + (uint32_t)((aRowB + mt * 16) * GSTR + ks * 8 + aColW) * 4);
#pragma unroll
            for (int bk = 0; bk < 4; bk++)
                ldsm4(b[2*bk][0], b[2*bk][1], b[2*bk+1][0], b[2*bk+1][1],
                      stW + (uint32_t)((bRowB + bk * 16) * GSTR + ks * 8 + bColW) * 4);
#pragma unroll
            for (int mt = 0; mt < 4; mt++)
#pragma unroll
                for (int nt = 0; nt < 8; nt++)
                    mma_tf(Cf[mt][nt], a[mt][0], a[mt][1], a[mt][2], a[mt][3],
                           b[nt][0], b[nt][1]);
        }
    }

    // epilogue
#pragma unroll
    for (int mt = 0; mt < 4; mt++) {
        int row0 = m0 + wm * 64 + mt * 16 + g;
#pragma unroll
        for (int nt = 0; nt < 8; nt++) {
            int col = n0 + wn * 64 + nt * 8 + 2 * j;
            float b0 = bias[col], b1 = bias[col + 1];
            float2 v0 = make_float2(Cf[mt][nt][0] + b0, Cf[mt][nt][1] + b1);
            float2 v1 = make_float2(Cf[mt][nt][2] + b0, Cf[mt][nt][3] + b1);
            if (MODE == 1) {
                *(float2*)(Cout + (size_t)row0 * DIMC + col) = v0;
                *(float2*)(Cout + (size_t)(row0 + 8) * DIMC + col) = v1;
            } else {
                int s = (col >= 2 * DIMC) ? 2 : (col >= DIMC ? 1 : 0);
                int rr = col - s * DIMC;
                int hh = rr / HD;
                int d = rr - hh * HD;
                int bb0 = row0 >> 11, t0 = row0 & (SEQ - 1);
                int r1 = row0 + 8;
                int bb1 = r1 >> 11, t1 = r1 & (SEQ - 1);
                if (s == 2) {
                    float* dv0 = g_vt + ((size_t)(bb0 * NH + hh) * HD + d) * SEQ + t0;
                    dv0[0] = v0.x; dv0[SEQ] = v0.y;
                    float* dv1 = g_vt + ((size_t)(bb1 * NH + hh) * HD + d) * SEQ + t1;
                    dv1[0] = v1.x; dv1[SEQ] = v1.y;
                } else {
                    float* base = (s == 0) ? g_q : g_k;
                    *(float2*)(base + ((size_t)(bb0 * NH + hh) * SEQ + t0) * HD + d) = v0;
                    *(float2*)(base + ((size_t)(bb1 * NH + hh) * SEQ + t1) * HD + d) = v1;
                }
            }
        }
    }
}

// ---------------------------------------------------------------------------
// RoPE in place on g_q, g_k.
// ---------------------------------------------------------------------------
__global__ __launch_bounds__(256)
void rope_kernel()
{
    int idx = blockIdx.x * blockDim.x + threadIdx.x;
    int j = idx % 48;
    int rest = idx / 48;
    int t = rest & (SEQ - 1);
    int bh = rest >> 11;

    float freq = exp2f(-(2.f * j / 96.f) * 13.287712379549449f);
    float ang = (float)t * freq;
    float sn, cs;
    sincosf(ang, &sn, &cs);

    size_t base = ((size_t)bh * SEQ + t) * HD;
    float q1 = g_q[base + j], q2 = g_q[base + j + 48];
    g_q[base + j]      = q1 * cs - q2 * sn;
    g_q[base + j + 48] = q2 * cs + q1 * sn;
    float k1 = g_k[base + j], k2 = g_k[base + j + 48];
    g_k[base + j]      = k1 * cs - k2 * sn;
    g_k[base + j + 48] = k2 * cs + k1 * sn;
}

// ---------------------------------------------------------------------------
// Flash attention v3: tf32 mma, ldmatrix fragments, V pre-transposed (g_vt),
// 3-stage cp.async K/Vt ring. Block = (qtile 128, h, b), 256 threads.
// ---------------------------------------------------------------------------
#define QLD 100
#define KLD 100
#define VTLD 68
#define KVSTG (64*KLD + 96*VTLD)
#define ATTN_SMEM ((128*QLD + 3*KVSTG) * 4)   // 206336

__global__ __launch_bounds__(256, 1)
void attn_mma()
{
    extern __shared__ float smf[];
    float* Qs = smf;
    float* KV = smf + 128 * QLD;

    int qt = gridDim.x - 1 - blockIdx.x;
    int hh = blockIdx.y, b = blockIdx.z;
    int tid = threadIdx.x;
    int lane = tid & 31;
    int wid = tid >> 5;
    int g = lane >> 2, j = lane & 3;
    const float scale = rsqrtf((float)HD);

    const float* Qg = g_q + ((size_t)(b * NH + hh) * SEQ + (size_t)qt * 128) * HD;
    const float* Kg = g_k + ((size_t)(b * NH + hh) * SEQ) * HD;
    const float* Vtg = g_vt + ((size_t)(b * NH + hh) * HD) * SEQ;

    int nkt = 2 * qt + 2;

    auto issue_kv = [&](int kt) {
        int st = kt % 3;
        float* Ks = KV + st * KVSTG;
        float* Vs = Ks + 64 * KLD;
        const float* kp = Kg + (size_t)kt * 64 * HD;
#pragma unroll
        for (int it = 0; it < 6; it++) {
            int f = tid + it * 256;
            int r = f / 24, c4 = (f % 24) * 4;
            cp16(smem_u32(Ks + r * KLD + c4), kp + (size_t)r * HD + c4);
        }
        const float* vp = Vtg + kt * 64;
#pragma unroll
        for (int it = 0; it < 6; it++) {
            int f = tid + it * 256;
            int d = f >> 4, c4 = (f & 15) * 4;
            cp16(smem_u32(Vs + d * VTLD + c4), vp + (size_t)d * SEQ + c4);
        }
    };

    issue_kv(0); cp_commit();
    issue_kv(1); cp_commit();

    for (int f = tid; f < 128 * 24; f += 256) {
        int r = f / 24, c4 = (f % 24) * 4;
        float4 v = *(const float4*)(Qg + (size_t)r * HD + c4);
        v.x = __uint_as_float(f2tf(v.x * scale));
        v.y = __uint_as_float(f2tf(v.y * scale));
        v.z = __uint_as_float(f2tf(v.z * scale));
        v.w = __uint_as_float(f2tf(v.w * scale));
        *(float4*)(Qs + r * QLD + c4) = v;
    }

    uint32_t qsb = smem_u32(Qs);
    int qRow = wid * 16 + ((lane >> 3) & 1) * 8 + (lane & 7);
    int qColW = (lane >> 4) * 4;
    int bRow = ((lane >> 4) & 1) * 8 + (lane & 7);
    int bColW = ((lane >> 3) & 1) * 4;

    float m0r = -1e30f, m1r = -1e30f, l0r = 0.f, l1r = 0.f;
    float O[12][4];
#pragma unroll
    for (int nt = 0; nt < 12; nt++)
#pragma unroll
        for (int r = 0; r < 4; r++) O[nt][r] = 0.f;

    int row0 = qt * 128 + wid * 16 + g;

    for (int kt = 0; kt < nkt; kt++) {
        cp_wait1();
        __syncthreads();
        if (kt + 2 < nkt) issue_kv(kt + 2);
        cp_commit();

        int st = kt % 3;
        uint32_t ksb = smem_u32(KV + st * KVSTG);
        uint32_t vsb = ksb + (uint32_t)(64 * KLD) * 4;

        float S[8][4];
#pragma unroll
        for (int nt = 0; nt < 8; nt++)
#pragma unroll
            for (int r = 0; r < 4; r++) S[nt][r] = 0.f;

#pragma unroll
        for (int ks = 0; ks < 12; ks++) {
            uint32_t a0, a1, a2, a3;
            ldsm4(a0, a1, a2, a3, qsb + (uint32_t)(qRow * QLD + ks * 8 + qColW) * 4);
            uint32_t bfr[8][2];
#pragma unroll
            for (int bk = 0; bk < 4; bk++)
                ldsm4(bfr[2*bk][0], bfr[2*bk][1], bfr[2*bk+1][0], bfr[2*bk+1][1],
                      ksb + (uint32_t)((bRow + bk * 16) * KLD + ks * 8 + bColW) * 4);
#pragma unroll
            for (int nt = 0; nt < 8; nt++)
                mma_tf(S[nt], a0, a1, a2, a3, bfr[nt][0], bfr[nt][1]);
        }

        if (kt >= nkt - 2) {
            int colb = kt * 64;
#pragma unroll
            for (int nt = 0; nt < 8; nt++) {
                int c0 = colb + nt * 8 + 2 * j;
                if (c0 > row0)     S[nt][0] = -1e30f;
                if (c0 + 1 > row0) S[nt][1] = -1e30f;
                if (c0 > row0 + 8)     S[nt][2] = -1e30f;
                if (c0 + 1 > row0 + 8) S[nt][3] = -1e30f;
            }
        }

        float mx0 = -1e30f, mx1 = -1e30f;
#pragma unroll
        for (int nt = 0; nt < 8; nt++) {
            mx0 = fmaxf(mx0, fmaxf(S[nt][0], S[nt][1]));
            mx1 = fmaxf(mx1, fmaxf(S[nt][2], S[nt][3]));
        }
        mx0 = fmaxf(mx0, __shfl_xor_sync(0xffffffffu, mx0, 1));
        mx0 = fmaxf(mx0, __shfl_xor_sync(0xffffffffu, mx0, 2));
        mx1 = fmaxf(mx1, __shfl_xor_sync(0xffffffffu, mx1, 1));
        mx1 = fmaxf(mx1, __shfl_xor_sync(0xffffffffu, mx1, 2));

        float mn0 = fmaxf(m0r, mx0), mn1 = fmaxf(m1r, mx1);
        float al0 = __expf(m0r - mn0), al1 = __expf(m1r - mn1);
        float s0 = 0.f, s1 = 0.f;
#pragma unroll
        for (int nt = 0; nt < 8; nt++) {
            S[nt][0] = __expf(S[nt][0] - mn0);
            S[nt][1] = __expf(S[nt][1] - mn0);
            S[nt][2] = __expf(S[nt][2] - mn1);
            S[nt][3] = __expf(S[nt][3] - mn1);
            s0 += S[nt][0] + S[nt][1];
            s1 += S[nt][2] + S[nt][3];
        }
        s0 += __shfl_xor_sync(0xffffffffu, s0, 1);
        s0 += __shfl_xor_sync(0xffffffffu, s0, 2);
        s1 += __shfl_xor_sync(0xffffffffu, s1, 1);
        s1 += __shfl_xor_sync(0xffffffffu, s1, 2);
        l0r = l0r * al0 + s0;
        l1r = l1r * al1 + s1;
        m0r = mn0; m1r = mn1;
#pragma unroll
        for (int nt = 0; nt < 12; nt++) {
            O[nt][0] *= al0; O[nt][1] *= al0;
            O[nt][2] *= al1; O[nt][3] *= al1;
        }

        int src_lo = (lane & ~3) | (j >> 1);
        int par = j & 1;
#pragma unroll
        for (int ks = 0; ks < 8; ks++) {
            float p00 = __shfl_sync(0xffffffffu, S[ks][0], src_lo);
            float p01 = __shfl_sync(0xffffffffu, S[ks][1], src_lo);
            float p10 = __shfl_sync(0xffffffffu, S[ks][0], src_lo + 2);
            float p11 = __shfl_sync(0xffffffffu, S[ks][1], src_lo + 2);
            float p20 = __shfl_sync(0xffffffffu, S[ks][2], src_lo);
            float p21 = __shfl_sync(0xffffffffu, S[ks][3], src_lo);
            float p30 = __shfl_sync(0xffffffffu, S[ks][2], src_lo + 2);
            float p31 = __shfl_sync(0xffffffffu, S[ks][3], src_lo + 2);
            uint32_t a0 = f2tf(par ? p01 : p00);
            uint32_t a1 = f2tf(par ? p21 : p20);
            uint32_t a2 = f2tf(par ? p11 : p10);
            uint32_t a3 = f2tf(par ? p31 : p30);
            uint32_t bfr[12][2];
#pragma unroll
            for (int bk = 0; bk < 6; bk++)
                ldsm4(bfr[2*bk][0], bfr[2*bk][1], bfr[2*bk+1][0], bfr[2*bk+1][1],
                      vsb + (uint32_t)((bRow + bk * 16) * VTLD + ks * 8 + bColW) * 4);
#pragma unroll
            for (int nt = 0; nt < 12; nt++)
                mma_tf(O[nt], a0, a1, a2, a3, bfr[nt][0], bfr[nt][1]);
        }
        __syncthreads();
    }

    float inv0 = 1.f / l0r, inv1 = 1.f / l1r;
    float* outb = g_att + ((size_t)b * SEQ + row0) * DIMC + hh * HD;
#pragma unroll
    for (int nt = 0; nt < 12; nt++) {
        int d = nt * 8 + 2 * j;
        float2 v0 = make_float2(__uint_as_float(f2tf(O[nt][0] * inv0)),
                                __uint_as_float(f2tf(O[nt][1] * inv0)));
        float2 v1 = make_float2(__uint_as_float(f2tf(O[nt][2] * inv1)),
                                __uint_as_float(f2tf(O[nt][3] * inv1)));
        *(float2*)(outb + d) = v0;
        *(float2*)(outb + (size_t)8 * DIMC + d) = v1;
    }
}

// ---------------------------------------------------------------------------
// Launch
// Inputs: 0=x, 1=mask (ignored, causal), 2=w_qkv, 3=b_qkv, 4=w_proj, 5=b_proj
// ---------------------------------------------------------------------------
extern "C" void kernel_launch(void* const* d_in, const int* in_sizes, int n_in,
                              void* d_out, int out_size)
{
    const float* x      = (const float*)d_in[0];
    const float* w_qkv  = (const float*)d_in[2];
    const float* b_qkv  = (const float*)d_in[3];
    const float* w_proj = (const float*)d_in[4];
    const float* b_proj = (const float*)d_in[5];
    float* out = (float*)d_out;

    cudaFuncSetAttribute(attn_mma, cudaFuncAttributeMaxDynamicSharedMemorySize,
                         ATTN_SMEM);
    cudaFuncSetAttribute(gemm_tf32<0>, cudaFuncAttributeMaxDynamicSharedMemorySize,
                         GEMM_SMEM_BYTES);
    cudaFuncSetAttribute(gemm_tf32<1>, cudaFuncAttributeMaxDynamicSharedMemorySize,
                         GEMM_SMEM_BYTES);

    float *xr, *wqr, *wpr, *attp;
    cudaGetSymbolAddress((void**)&xr,  g_xr);
    cudaGetSymbolAddress((void**)&wqr, g_wqr);
    cudaGetSymbolAddress((void**)&wpr, g_wpr);
    cudaGetSymbolAddress((void**)&attp, g_att);

    // tf32-round operands (removes truncation bias in mma)
    round_tf_kernel<<<(MTOT * DIMC / 4 + 255) / 256, 256>>>(x, xr, MTOT * DIMC / 4);
    round_tf_kernel<<<(3 * DIMC * DIMC / 4 + 255) / 256, 256>>>(w_qkv, wqr, 3 * DIMC * DIMC / 4);
    round_tf_kernel<<<(DIMC * DIMC / 4 + 255) / 256, 256>>>(w_proj, wpr, DIMC * DIMC / 4);

    // QKV: M=8192, N=2304 (CTA tile 128x256)
    gemm_tf32<0><<<dim3(2304 / 256, MTOT / 128), 256, GEMM_SMEM_BYTES>>>(
        xr, wqr, b_qkv, nullptr);

    // RoPE
    rope_kernel<<<(BATCH * NH * SEQ * 48) / 256, 256>>>();

    // Attention
    attn_mma<<<dim3(SEQ / 128, NH, BATCH), 256, ATTN_SMEM>>>();

    // Projection: M=8192, N=768
    gemm_tf32<1><<<dim3(DIMC / 256, MTOT / 128), 256, GEMM_SMEM_BYTES>>>(
        attp, wpr, b_proj, out);
}